// round 3
// baseline (speedup 1.0000x reference)
#include <cuda_runtime.h>
#include <math.h>

// B=8, n=32, C=64, O=64
// in: 0 x0[8,64] 1 x1[8,32,64] 2 x2[8,32,32,64] 3 x3[8,32,32,32,64]
// 4 w_op0 5 b_op0 6 w_red0 7 b_red0 8 w_exp1 9 b_exp1 10 w_op1 11 b_op1
// 12 w_red1 13 b_red1 14 w_exp2 15 b_exp2 16 w_op2 17 b_op2 18 w_red2 19 b_red2
// 20 w_exp3 21 b_exp3 22 w_op3 23 b_op3 24 act[8,10] i32
// out: concat(o0[8,64], o1[8,32,64], o2[8,32,32,64], o3[8,32,32,32,64]) f32

#define O1_OFF 512
#define O2_OFF 16896
#define O3_OFF 541184

__device__ __align__(16) float g_We3T[384 * 64];
__device__ __align__(16) float g_Wt3[8 * 384 * 64];
__device__ __align__(16) float g_Wt2[8 * 512 * 64];
__device__ __align__(16) float g_bias3[8 * 64];
__device__ __align__(16) float g_bias2[8 * 64];
__device__ __align__(16) float g_scal[8 * 10];
__device__ int g_flags[4];
__device__ __align__(16) float g_r1[8 * 128];
__device__ __align__(16) float g_r2[8 * 32 * 128];
__device__ __align__(16) float g_r3[8 * 32 * 32 * 128];
__device__ __align__(16) float g_y2[8 * 32 * 32 * 384];
__device__ __align__(16) float g_P1[8 * 32 * 32 * 64];
__device__ __align__(16) float g_P2[8 * 32 * 32 * 64];
__device__ __align__(16) float g_P3[8 * 32 * 32 * 64];

__device__ __forceinline__ float sigf(float x) { return 1.0f / (1.0f + __expf(-x)); }

// ------------------------------- prep -------------------------------------
__global__ void prep_kernel(const float* __restrict__ w_exp3, const float* __restrict__ w_op3,
                            const float* __restrict__ w_exp2, const float* __restrict__ w_op2,
                            const float* __restrict__ w_red2, const float* __restrict__ b_exp3,
                            const float* __restrict__ b_op3, const float* __restrict__ b_exp2,
                            const float* __restrict__ b_op2, const float* __restrict__ b_red2,
                            const int* __restrict__ act) {
    int t = blockIdx.x * blockDim.x + threadIdx.x;
    int nth = gridDim.x * blockDim.x;
    if (t < 80) g_scal[t] = (float)act[t];
    if (t == 0) {
        int f0 = 0, f1 = 0, f2 = 0, f3 = 0;
        for (int b = 0; b < 8; b++) {
            f0 |= act[b * 10 + 0] | act[b * 10 + 1];
            f1 |= act[b * 10 + 2] | act[b * 10 + 3] | act[b * 10 + 4];
            f2 |= act[b * 10 + 5] | act[b * 10 + 6] | act[b * 10 + 7];
            f3 |= act[b * 10 + 8] | act[b * 10 + 9];
        }
        g_flags[0] = f0; g_flags[1] = f1; g_flags[2] = f2; g_flags[3] = f3;
    }
    for (int f = t; f < 24576; f += nth) {          // We3T[c*384 + m*64 + o]
        int o = f / 384, r = f % 384, m = r >> 6, c = r & 63;
        g_We3T[c * 384 + m * 64 + o] = w_exp3[f];
    }
    for (int f = t; f < 8 * 24576; f += nth) {      // Wt3[b][cidx][o] = a9*w_op3[o][cidx]
        int b = f / 24576, r = f % 24576;
        int o = r & 63, cidx = r >> 6;
        g_Wt3[f] = (float)act[b * 10 + 9] * w_op3[o * 384 + cidx];
    }
    for (int f = t; f < 8 * 32768; f += nth) {      // Wt2[b][cp][o]
        int b = f >> 15, r = f & 32767;
        int o = r & 63, cp = r >> 6;
        float v;
        if (cp < 128)      v = (float)act[b * 10 + 5] * w_exp2[o * 128 + cp];
        else if (cp < 256) v = (float)act[b * 10 + 6] * w_op2[o * 128 + (cp - 128)];
        else               v = (float)act[b * 10 + 7] * w_red2[o * 256 + (cp - 256)];
        g_Wt2[f] = v;
    }
    for (int f = t; f < 512; f += nth) {
        int b = f >> 6, o = f & 63;
        g_bias3[f] = (float)act[b * 10 + 8] * b_exp3[o] + (float)act[b * 10 + 9] * b_op3[o];
        g_bias2[f] = (float)act[b * 10 + 5] * b_exp2[o] + (float)act[b * 10 + 6] * b_op2[o]
                   + (float)act[b * 10 + 7] * b_red2[o];
    }
}

// ----------------------------- reductions ----------------------------------
__global__ void reduce1_kernel(const float* __restrict__ x1) {
    int b = blockIdx.x, c = threadIdx.x;
    float ex = -INFINITY, fa = INFINITY;
    for (int i = 0; i < 32; i++) {
        float v = x1[(b * 32 + i) * 64 + c];
        ex = fmaxf(ex, v); fa = fminf(fa, v);
    }
    g_r1[b * 128 + 2 * c] = ex;
    g_r1[b * 128 + 2 * c + 1] = fa;
}

__global__ void reduce2_kernel(const float* __restrict__ x2) {
    int blk = blockIdx.x;  // b*32+i
    int c = threadIdx.x;
    int i = blk & 31;
    const float* base = x2 + (size_t)blk * 2048;
    float ex = 0.0f, fa = 1.0f;   // masked slot contributes 0 / 1
    for (int j = 0; j < 32; j++) {
        if (j == i) continue;
        float v = base[j * 64 + c];
        ex = fmaxf(ex, v); fa = fminf(fa, v);
    }
    g_r2[blk * 128 + 2 * c] = ex;
    g_r2[blk * 128 + 2 * c + 1] = fa;
}

__global__ void reduce3_kernel(const float* __restrict__ x3) {
    int blk = blockIdx.x;  // b*1024 + i*32 + j
    int c = threadIdx.x;
    int i = (blk >> 5) & 31, j = blk & 31;
    float ex = 0.0f, fa = 1.0f;
    if (i != j) {
        const float* base = x3 + (size_t)blk * 2048;
        for (int k = 0; k < 32; k++) {
            if (k == i || k == j) continue;
            float v = base[k * 64 + c];
            ex = fmaxf(ex, v); fa = fminf(fa, v);
        }
    }
    g_r3[(size_t)blk * 128 + 2 * c] = ex;
    g_r3[(size_t)blk * 128 + 2 * c + 1] = fa;
}

// ------------- y2[b,p,q, m*64+o] = sum_c x2[b,p,q,c] * w_exp3[o, m*64+c] ----
__global__ void __launch_bounds__(384) y2_kernel(const float* __restrict__ x2) {
    __shared__ float Ash[2048];
    __shared__ float Wsh[16 * 384];
    int tid = threadIdx.x;        // output column
    int blk = blockIdx.x;         // b*32 + p
    for (int f = tid; f < 2048; f += 384) Ash[f] = x2[(size_t)blk * 2048 + f];
    float acc[32];
#pragma unroll
    for (int q = 0; q < 32; q++) acc[q] = 0.0f;
    for (int cc = 0; cc < 4; cc++) {
        __syncthreads();
#pragma unroll
        for (int it = 0; it < 16; it++)
            Wsh[it * 384 + tid] = g_We3T[cc * 6144 + it * 384 + tid];
        __syncthreads();
#pragma unroll
        for (int q = 0; q < 32; q++) {
            float s = acc[q];
#pragma unroll
            for (int c2 = 0; c2 < 16; c2++)
                s = fmaf(Ash[q * 64 + cc * 16 + c2], Wsh[c2 * 384 + tid], s);
            acc[q] = s;
        }
    }
#pragma unroll
    for (int q = 0; q < 32; q++)
        g_y2[((size_t)blk * 32 + q) * 384 + tid] = acc[q];
}

// ----------------- pair sums P1/P2/P3 (a8 + bias folded) --------------------
__global__ void psum_kernel() {
    int t = blockIdx.x * blockDim.x + threadIdx.x;   // 524288
    int o = t & 63, q = (t >> 6) & 31, p = (t >> 11) & 31, b = t >> 16;
    float a8 = g_scal[b * 10 + 8];
    size_t pq = ((size_t)(b * 32 + p) * 32 + q) * 384;
    size_t qp = ((size_t)(b * 32 + q) * 32 + p) * 384;
    g_P1[t] = a8 * (g_y2[pq + o] + g_y2[qp + 128 + o]) + g_bias3[b * 64 + o];
    g_P2[t] = a8 * (g_y2[pq + 64 + o] + g_y2[qp + 192 + o]);
    g_P3[t] = a8 * (g_y2[pq + 256 + o] + g_y2[qp + 320 + o]);
}

// ------------------------------- o0 / o1 -----------------------------------
__global__ void o0_kernel(const float* __restrict__ x0,
                          const float* __restrict__ w_op0, const float* __restrict__ b_op0,
                          const float* __restrict__ w_red0, const float* __restrict__ b_red0,
                          float* __restrict__ out) {
    int b = blockIdx.x, o = threadIdx.x;
    __shared__ float xs[64], rs[128];
    xs[o] = x0[b * 64 + o];
    rs[o] = g_r1[b * 128 + o];
    rs[o + 64] = g_r1[b * 128 + 64 + o];
    __syncthreads();
    float d0 = 0.0f, d1 = 0.0f;
#pragma unroll 8
    for (int c = 0; c < 64; c++) d0 = fmaf(w_op0[o * 64 + c], xs[c], d0);
#pragma unroll 8
    for (int c = 0; c < 128; c++) d1 = fmaf(w_red0[o * 128 + c], rs[c], d1);
    float s = g_scal[b * 10 + 0] * (d0 + b_op0[o]) + g_scal[b * 10 + 1] * (d1 + b_red0[o]);
    out[b * 64 + o] = g_flags[0] ? sigf(s) : 0.0f;
}

__global__ void o1_kernel(const float* __restrict__ x0, const float* __restrict__ x1,
                          const float* __restrict__ w_exp1, const float* __restrict__ b_exp1,
                          const float* __restrict__ w_op1, const float* __restrict__ b_op1,
                          const float* __restrict__ w_red1, const float* __restrict__ b_red1,
                          float* __restrict__ out) {
    int blk = blockIdx.x;  // b*32+i
    int b = blk >> 5, o = threadIdx.x;
    __shared__ float x0s[64], x1s[64], r2s[128];
    x0s[o] = x0[b * 64 + o];
    x1s[o] = x1[blk * 64 + o];
    r2s[o] = g_r2[blk * 128 + o];
    r2s[o + 64] = g_r2[blk * 128 + 64 + o];
    __syncthreads();
    float d0 = 0.0f, d1 = 0.0f, d2 = 0.0f;
#pragma unroll 8
    for (int c = 0; c < 64; c++) {
        d0 = fmaf(w_exp1[o * 64 + c], x0s[c], d0);
        d1 = fmaf(w_op1[o * 64 + c], x1s[c], d1);
    }
#pragma unroll 8
    for (int c = 0; c < 128; c++) d2 = fmaf(w_red1[o * 128 + c], r2s[c], d2);
    float s = g_scal[b * 10 + 2] * (d0 + b_exp1[o]) + g_scal[b * 10 + 3] * (d1 + b_op1[o])
            + g_scal[b * 10 + 4] * (d2 + b_red1[o]);
    out[O1_OFF + blk * 64 + o] = g_flags[1] ? sigf(s) : 0.0f;
}

// ------------------- main: o3 (blocks 0..2047) + o2 (2048..2111) ------------
__device__ __forceinline__ void mm_chunk(const float* __restrict__ As,
                                         const float* __restrict__ Ws,
                                         float acc[8][4], int r0, int tx) {
#pragma unroll 8
    for (int k = 0; k < 32; k++) {
        float4 w = *(const float4*)(Ws + k * 64 + tx * 4);
#pragma unroll
        for (int u = 0; u < 8; u++) {
            float a = As[(r0 + u) * 36 + k];
            acc[u][0] = fmaf(a, w.x, acc[u][0]);
            acc[u][1] = fmaf(a, w.y, acc[u][1]);
            acc[u][2] = fmaf(a, w.z, acc[u][2]);
            acc[u][3] = fmaf(a, w.w, acc[u][3]);
        }
    }
}

__global__ void __launch_bounds__(256) main_kernel(const float* __restrict__ x1,
                                                   const float* __restrict__ x2,
                                                   const float* __restrict__ x3,
                                                   float* __restrict__ out) {
    __shared__ float As[128 * 36];
    __shared__ float Ws[32 * 64];
    int tid = threadIdx.x;
    int tx = tid & 15, ty = tid >> 4;
    int r0 = ty * 8;
    int bid = blockIdx.x;
    float acc[8][4];
#pragma unroll
    for (int u = 0; u < 8; u++)
#pragma unroll
        for (int v = 0; v < 4; v++) acc[u][v] = 0.0f;

    if (bid < 2048) {
        // ---- o3: block (b, i, j-quad) ----
        int b = bid >> 8, r = bid & 255, i = r >> 3, j0 = (r & 7) << 2;
        const float* X = x3 + ((size_t)b << 21);
        const float* Wb = g_Wt3 + b * 24576;
        for (int ch = 0; ch < 12; ch++) {
            int m = ch >> 1, c0 = (ch & 1) << 5;
            __syncthreads();
            const float4* ws = (const float4*)(Wb + ch * 2048);
            ((float4*)Ws)[tid] = ws[tid];
            ((float4*)Ws)[tid + 256] = ws[tid + 256];
#pragma unroll
            for (int it = 0; it < 4; it++) {
                int idx = tid + it * 256;
                int row = idx >> 3, seg = idx & 7;
                int jj = row >> 5, k = row & 31, j = j0 + jj;
                int xr;
                switch (m) {
                    case 0:  xr = (i * 32 + j) * 32 + k; break;
                    case 1:  xr = (i * 32 + k) * 32 + j; break;
                    case 2:  xr = (j * 32 + i) * 32 + k; break;
                    case 3:  xr = (k * 32 + i) * 32 + j; break;
                    case 4:  xr = (j * 32 + k) * 32 + i; break;
                    default: xr = (k * 32 + j) * 32 + i; break;
                }
                *(float4*)(As + row * 36 + seg * 4) =
                    *(const float4*)(X + (size_t)xr * 64 + c0 + seg * 4);
            }
            __syncthreads();
            mm_chunk(As, Ws, acc, r0, tx);
        }
        int j = j0 + (ty >> 2), k0 = (ty & 3) * 8;
        int flag = g_flags[3];
        float4 p1 = *(const float4*)(g_P1 + (((b * 32 + i) * 32 + j) << 6) + tx * 4);
#pragma unroll
        for (int u = 0; u < 8; u++) {
            int k = k0 + u;
            float4 p2 = *(const float4*)(g_P2 + (((b * 32 + i) * 32 + k) << 6) + tx * 4);
            float4 p3 = *(const float4*)(g_P3 + (((b * 32 + j) * 32 + k) << 6) + tx * 4);
            float4 rO;
            rO.x = acc[u][0] + p1.x + p2.x + p3.x;
            rO.y = acc[u][1] + p1.y + p2.y + p3.y;
            rO.z = acc[u][2] + p1.z + p2.z + p3.z;
            rO.w = acc[u][3] + p1.w + p2.w + p3.w;
            if (flag) { rO.x = sigf(rO.x); rO.y = sigf(rO.y); rO.z = sigf(rO.z); rO.w = sigf(rO.w); }
            else      { rO.x = rO.y = rO.z = rO.w = 0.0f; }
            size_t oidx = O3_OFF + ((((size_t)(b * 32 + i) * 32 + j) * 32 + k) << 6) + tx * 4;
            *(float4*)(out + oidx) = rO;
        }
    } else {
        // ---- o2: block (b, i-quad) ----
        int bid2 = bid - 2048;
        int b = bid2 >> 3, i0 = (bid2 & 7) << 2;
        const float* Wb = g_Wt2 + (size_t)b * 32768;
        for (int ch = 0; ch < 16; ch++) {
            __syncthreads();
            const float4* ws = (const float4*)(Wb + ch * 2048);
            ((float4*)Ws)[tid] = ws[tid];
            ((float4*)Ws)[tid + 256] = ws[tid + 256];
#pragma unroll
            for (int it = 0; it < 4; it++) {
                int idx = tid + it * 256;
                int row = idx >> 3, seg = idx & 7;
                int ii = row >> 5, j = row & 31, i = i0 + ii;
                int cp = ch * 32 + seg * 4;
                const float* src;
                if (cp < 64)       src = x1 + (b * 32 + i) * 64 + cp;
                else if (cp < 128) src = x1 + (b * 32 + j) * 64 + (cp - 64);
                else if (cp < 192) src = x2 + ((size_t)(b * 32 + i) * 32 + j) * 64 + (cp - 128);
                else if (cp < 256) src = x2 + ((size_t)(b * 32 + j) * 32 + i) * 64 + (cp - 192);
                else if (cp < 384) src = g_r3 + ((size_t)(b * 32 + i) * 32 + j) * 128 + (cp - 256);
                else               src = g_r3 + ((size_t)(b * 32 + j) * 32 + i) * 128 + (cp - 384);
                *(float4*)(As + row * 36 + seg * 4) = *(const float4*)src;
            }
            __syncthreads();
            mm_chunk(As, Ws, acc, r0, tx);
        }
        int i = i0 + (ty >> 2), j0k = (ty & 3) * 8;
        int flag = g_flags[2];
        float4 bs = *(const float4*)(g_bias2 + b * 64 + tx * 4);
#pragma unroll
        for (int u = 0; u < 8; u++) {
            int j = j0k + u;
            float4 rO;
            rO.x = acc[u][0] + bs.x;
            rO.y = acc[u][1] + bs.y;
            rO.z = acc[u][2] + bs.z;
            rO.w = acc[u][3] + bs.w;
            if (flag) { rO.x = sigf(rO.x); rO.y = sigf(rO.y); rO.z = sigf(rO.z); rO.w = sigf(rO.w); }
            else      { rO.x = rO.y = rO.z = rO.w = 0.0f; }
            size_t oidx = O2_OFF + (((size_t)(b * 32 + i) * 32 + j) << 6) + tx * 4;
            *(float4*)(out + oidx) = rO;
        }
    }
}

// ------------------------------- launch -------------------------------------
extern "C" void kernel_launch(void* const* d_in, const int* in_sizes, int n_in,
                              void* d_out, int out_size) {
    const float* x0 = (const float*)d_in[0];
    const float* x1 = (const float*)d_in[1];
    const float* x2 = (const float*)d_in[2];
    const float* x3 = (const float*)d_in[3];
    const float* w_op0 = (const float*)d_in[4];
    const float* b_op0 = (const float*)d_in[5];
    const float* w_red0 = (const float*)d_in[6];
    const float* b_red0 = (const float*)d_in[7];
    const float* w_exp1 = (const float*)d_in[8];
    const float* b_exp1 = (const float*)d_in[9];
    const float* w_op1 = (const float*)d_in[10];
    const float* b_op1 = (const float*)d_in[11];
    const float* w_red1 = (const float*)d_in[12];
    const float* b_red1 = (const float*)d_in[13];
    const float* w_exp2 = (const float*)d_in[14];
    const float* b_exp2 = (const float*)d_in[15];
    const float* w_op2 = (const float*)d_in[16];
    const float* b_op2 = (const float*)d_in[17];
    const float* w_red2 = (const float*)d_in[18];
    const float* b_red2 = (const float*)d_in[19];
    const float* w_exp3 = (const float*)d_in[20];
    const float* b_exp3 = (const float*)d_in[21];
    const float* w_op3 = (const float*)d_in[22];
    const float* b_op3 = (const float*)d_in[23];
    const int* act = (const int*)d_in[24];
    float* out = (float*)d_out;

    prep_kernel<<<64, 256>>>(w_exp3, w_op3, w_exp2, w_op2, w_red2,
                             b_exp3, b_op3, b_exp2, b_op2, b_red2, act);
    reduce1_kernel<<<8, 64>>>(x1);
    reduce2_kernel<<<256, 64>>>(x2);
    reduce3_kernel<<<8192, 64>>>(x3);
    y2_kernel<<<256, 384>>>(x2);
    psum_kernel<<<2048, 256>>>();
    o0_kernel<<<8, 64>>>(x0, w_op0, b_op0, w_red0, b_red0, out);
    o1_kernel<<<256, 64>>>(x0, x1, w_exp1, b_exp1, w_op1, b_op1, w_red1, b_red1, out);
    main_kernel<<<2112, 256>>>(x1, x2, x3, out);
}

// round 4
// speedup vs baseline: 1.0928x; 1.0928x over previous
#include <cuda_runtime.h>
#include <math.h>

// B=8, n=32, C=64, O=64
// out: concat(o0[8,64], o1[8,32,64], o2[8,32,32,64], o3[8,32,32,32,64]) f32

#define O1_OFF 512
#define O2_OFF 16896
#define O3_OFF 541184

#define FMA2(d, a, b) asm("fma.rn.f32x2 %0, %1, %2, %0;" : "+l"(d) : "l"(a), "l"(b))

__device__ __align__(16) float g_We3T[384 * 64];
__device__ __align__(16) float g_Wt3[8 * 12 * 64 * 32];   // [b][chunk][o][k]
__device__ __align__(16) float g_Wt2[8 * 16 * 64 * 32];   // [b][chunk][o][k]
__device__ __align__(16) float g_bias3[8 * 64];
__device__ __align__(16) float g_bias2[8 * 64];
__device__ __align__(16) float g_scal[8 * 10];
__device__ int g_flags[4];
__device__ __align__(16) float g_r1[8 * 128];
__device__ __align__(16) float g_r2[8 * 32 * 128];
__device__ __align__(16) float g_r3[8 * 32 * 32 * 128];
__device__ __align__(16) float g_y2[8 * 32 * 32 * 384];
__device__ __align__(16) float g_P1[8 * 32 * 32 * 64];
__device__ __align__(16) float g_P2[8 * 32 * 32 * 64];
__device__ __align__(16) float g_P3[8 * 32 * 32 * 64];

__device__ __forceinline__ float sigf(float x) { return 1.0f / (1.0f + __expf(-x)); }

// ------------------------------- prep -------------------------------------
__global__ void prep_kernel(const float* __restrict__ w_exp3, const float* __restrict__ w_op3,
                            const float* __restrict__ w_exp2, const float* __restrict__ w_op2,
                            const float* __restrict__ w_red2, const float* __restrict__ b_exp3,
                            const float* __restrict__ b_op3, const float* __restrict__ b_exp2,
                            const float* __restrict__ b_op2, const float* __restrict__ b_red2,
                            const int* __restrict__ act) {
    int t = blockIdx.x * blockDim.x + threadIdx.x;
    int nth = gridDim.x * blockDim.x;
    if (t < 80) g_scal[t] = (float)act[t];
    if (t == 0) {
        int f0 = 0, f1 = 0, f2 = 0, f3 = 0;
        for (int b = 0; b < 8; b++) {
            f0 |= act[b * 10 + 0] | act[b * 10 + 1];
            f1 |= act[b * 10 + 2] | act[b * 10 + 3] | act[b * 10 + 4];
            f2 |= act[b * 10 + 5] | act[b * 10 + 6] | act[b * 10 + 7];
            f3 |= act[b * 10 + 8] | act[b * 10 + 9];
        }
        g_flags[0] = f0; g_flags[1] = f1; g_flags[2] = f2; g_flags[3] = f3;
    }
    for (int f = t; f < 24576; f += nth) {          // We3T[c*384 + m*64 + o]
        int o = f / 384, r = f % 384, m = r >> 6, c = r & 63;
        g_We3T[c * 384 + m * 64 + o] = w_exp3[f];
    }
    // Wt3[b][ch][o][k] = a9 * w_op3[o][ch*32+k]
    for (int f = t; f < 8 * 24576; f += nth) {
        int b = f / 24576, r = f % 24576;
        int ch = r >> 11, o = (r >> 5) & 63, k = r & 31;
        g_Wt3[f] = (float)act[b * 10 + 9] * w_op3[o * 384 + ch * 32 + k];
    }
    // Wt2[b][ch][o][k], cp = ch*32+k
    for (int f = t; f < 8 * 32768; f += nth) {
        int b = f >> 15, r = f & 32767;
        int ch = r >> 11, o = (r >> 5) & 63, k = r & 31;
        int cp = ch * 32 + k;
        float v;
        if (cp < 128)      v = (float)act[b * 10 + 5] * w_exp2[o * 128 + cp];
        else if (cp < 256) v = (float)act[b * 10 + 6] * w_op2[o * 128 + (cp - 128)];
        else               v = (float)act[b * 10 + 7] * w_red2[o * 256 + (cp - 256)];
        g_Wt2[f] = v;
    }
    for (int f = t; f < 512; f += nth) {
        int b = f >> 6, o = f & 63;
        g_bias3[f] = (float)act[b * 10 + 8] * b_exp3[o] + (float)act[b * 10 + 9] * b_op3[o];
        g_bias2[f] = (float)act[b * 10 + 5] * b_exp2[o] + (float)act[b * 10 + 6] * b_op2[o]
                   + (float)act[b * 10 + 7] * b_red2[o];
    }
}

// ----------------------------- reductions ----------------------------------
__global__ void reduce1_kernel(const float* __restrict__ x1) {
    int b = blockIdx.x, c = threadIdx.x;
    float ex = -INFINITY, fa = INFINITY;
    for (int i = 0; i < 32; i++) {
        float v = x1[(b * 32 + i) * 64 + c];
        ex = fmaxf(ex, v); fa = fminf(fa, v);
    }
    g_r1[b * 128 + 2 * c] = ex;
    g_r1[b * 128 + 2 * c + 1] = fa;
}

__global__ void reduce2_kernel(const float* __restrict__ x2) {
    int blk = blockIdx.x;  // b*32+i
    int c = threadIdx.x;
    int i = blk & 31;
    const float* base = x2 + (size_t)blk * 2048;
    float ex = 0.0f, fa = 1.0f;
    for (int j = 0; j < 32; j++) {
        if (j == i) continue;
        float v = base[j * 64 + c];
        ex = fmaxf(ex, v); fa = fminf(fa, v);
    }
    g_r2[blk * 128 + 2 * c] = ex;
    g_r2[blk * 128 + 2 * c + 1] = fa;
}

__global__ void reduce3_kernel(const float* __restrict__ x3) {
    int blk = blockIdx.x;  // b*1024 + i*32 + j
    int c = threadIdx.x;
    int i = (blk >> 5) & 31, j = blk & 31;
    float ex0 = 0.0f, fa0 = 1.0f, ex1 = 0.0f, fa1 = 1.0f;
    if (i != j) {
        const float* base = x3 + (size_t)blk * 2048 + c;
#pragma unroll 4
        for (int k = 0; k < 32; k += 2) {
            float v0 = base[k * 64];
            float v1 = base[(k + 1) * 64];
            if (k != i && k != j)         { ex0 = fmaxf(ex0, v0); fa0 = fminf(fa0, v0); }
            if (k + 1 != i && k + 1 != j) { ex1 = fmaxf(ex1, v1); fa1 = fminf(fa1, v1); }
        }
    }
    float2 r;
    r.x = fmaxf(ex0, ex1);
    r.y = fminf(fa0, fa1);
    if (i == j) { r.x = 0.0f; r.y = 1.0f; }
    *(float2*)(g_r3 + (size_t)blk * 128 + 2 * c) = r;
}

// ------------- y2[b,p,q, m*64+o] = sum_c x2[b,p,q,c] * w_exp3[o, m*64+c] ----
__global__ void __launch_bounds__(384) y2_kernel(const float* __restrict__ x2) {
    __shared__ float Ash[2048];
    __shared__ float Wsh[16 * 384];
    int tid = threadIdx.x;
    int blk = blockIdx.x;         // b*32 + p
    for (int f = tid; f < 2048; f += 384) Ash[f] = x2[(size_t)blk * 2048 + f];
    float acc[32];
#pragma unroll
    for (int q = 0; q < 32; q++) acc[q] = 0.0f;
    for (int cc = 0; cc < 4; cc++) {
        __syncthreads();
#pragma unroll
        for (int it = 0; it < 16; it++)
            Wsh[it * 384 + tid] = g_We3T[cc * 6144 + it * 384 + tid];
        __syncthreads();
#pragma unroll
        for (int q = 0; q < 32; q++) {
            float s = acc[q];
#pragma unroll
            for (int c2 = 0; c2 < 16; c2++)
                s = fmaf(Ash[q * 64 + cc * 16 + c2], Wsh[c2 * 384 + tid], s);
            acc[q] = s;
        }
    }
#pragma unroll
    for (int q = 0; q < 32; q++)
        g_y2[((size_t)blk * 32 + q) * 384 + tid] = acc[q];
}

// ----------------- pair sums P1/P2/P3 (a8 + bias folded) --------------------
__global__ void psum_kernel() {
    int t = blockIdx.x * blockDim.x + threadIdx.x;   // 524288
    int o = t & 63, q = (t >> 6) & 31, p = (t >> 11) & 31, b = t >> 16;
    float a8 = g_scal[b * 10 + 8];
    size_t pq = ((size_t)(b * 32 + p) * 32 + q) * 384;
    size_t qp = ((size_t)(b * 32 + q) * 32 + p) * 384;
    g_P1[t] = a8 * (g_y2[pq + o] + g_y2[qp + 128 + o]) + g_bias3[b * 64 + o];
    g_P2[t] = a8 * (g_y2[pq + 64 + o] + g_y2[qp + 192 + o]);
    g_P3[t] = a8 * (g_y2[pq + 256 + o] + g_y2[qp + 320 + o]);
}

// ------------------------------- o0 / o1 -----------------------------------
__global__ void o0_kernel(const float* __restrict__ x0,
                          const float* __restrict__ w_op0, const float* __restrict__ b_op0,
                          const float* __restrict__ w_red0, const float* __restrict__ b_red0,
                          float* __restrict__ out) {
    int b = blockIdx.x, o = threadIdx.x;
    __shared__ float xs[64], rs[128];
    xs[o] = x0[b * 64 + o];
    rs[o] = g_r1[b * 128 + o];
    rs[o + 64] = g_r1[b * 128 + 64 + o];
    __syncthreads();
    float d0 = 0.0f, d1 = 0.0f;
#pragma unroll 8
    for (int c = 0; c < 64; c++) d0 = fmaf(w_op0[o * 64 + c], xs[c], d0);
#pragma unroll 8
    for (int c = 0; c < 128; c++) d1 = fmaf(w_red0[o * 128 + c], rs[c], d1);
    float s = g_scal[b * 10 + 0] * (d0 + b_op0[o]) + g_scal[b * 10 + 1] * (d1 + b_red0[o]);
    out[b * 64 + o] = g_flags[0] ? sigf(s) : 0.0f;
}

__global__ void o1_kernel(const float* __restrict__ x0, const float* __restrict__ x1,
                          const float* __restrict__ w_exp1, const float* __restrict__ b_exp1,
                          const float* __restrict__ w_op1, const float* __restrict__ b_op1,
                          const float* __restrict__ w_red1, const float* __restrict__ b_red1,
                          float* __restrict__ out) {
    int blk = blockIdx.x;  // b*32+i
    int b = blk >> 5, o = threadIdx.x;
    __shared__ float x0s[64], x1s[64], r2s[128];
    x0s[o] = x0[b * 64 + o];
    x1s[o] = x1[blk * 64 + o];
    r2s[o] = g_r2[blk * 128 + o];
    r2s[o + 64] = g_r2[blk * 128 + 64 + o];
    __syncthreads();
    float d0 = 0.0f, d1 = 0.0f, d2 = 0.0f;
#pragma unroll 8
    for (int c = 0; c < 64; c++) {
        d0 = fmaf(w_exp1[o * 64 + c], x0s[c], d0);
        d1 = fmaf(w_op1[o * 64 + c], x1s[c], d1);
    }
#pragma unroll 8
    for (int c = 0; c < 128; c++) d2 = fmaf(w_red1[o * 128 + c], r2s[c], d2);
    float s = g_scal[b * 10 + 2] * (d0 + b_exp1[o]) + g_scal[b * 10 + 3] * (d1 + b_op1[o])
            + g_scal[b * 10 + 4] * (d2 + b_red1[o]);
    out[O1_OFF + blk * 64 + o] = g_flags[1] ? sigf(s) : 0.0f;
}

// ------------------- main: o3 (blocks 0..2047) + o2 (2048..2111) ------------
// As: [row 0..127][k 0..31] row-major.  Ws: [col][k] with XOR swizzle.
// K-parity packing: lo/hi halves of f32x2 accumulate disjoint k partial sums.
__device__ __forceinline__ void mm_chunk2(const float* __restrict__ As,
                                          const float* __restrict__ Ws,
                                          unsigned long long acc2[8][4], int r0, int tx) {
    int swz = (tx & 7) << 2;
#pragma unroll
    for (int kq = 0; kq < 8; kq++) {
        int kk = (kq * 4) ^ swz;
        ulonglong2 w[4];
#pragma unroll
        for (int v = 0; v < 4; v++)
            w[v] = *(const ulonglong2*)(Ws + (tx * 4 + v) * 32 + kk);
#pragma unroll
        for (int u = 0; u < 8; u++) {
            ulonglong2 a = *(const ulonglong2*)(As + (r0 + u) * 32 + kq * 4);
#pragma unroll
            for (int v = 0; v < 4; v++) {
                FMA2(acc2[u][v], a.x, w[v].x);
                FMA2(acc2[u][v], a.y, w[v].y);
            }
        }
    }
}

union F2U { unsigned long long u; float2 f; };

__global__ void __launch_bounds__(256, 2) main_kernel(const float* __restrict__ x1,
                                                      const float* __restrict__ x2,
                                                      const float* __restrict__ x3,
                                                      float* __restrict__ out) {
    __shared__ float As[128 * 32];
    __shared__ float Ws[64 * 32];
    int tid = threadIdx.x;
    int tx = tid & 15, ty = tid >> 4;
    int r0 = ty * 8;
    int bid = blockIdx.x;
    unsigned long long acc2[8][4];
#pragma unroll
    for (int u = 0; u < 8; u++)
#pragma unroll
        for (int v = 0; v < 4; v++) acc2[u][v] = 0ull;

    if (bid < 2048) {
        // ---- o3: block (b, i, j-quad) ----
        int b = bid >> 8, r = bid & 255, i = r >> 3, j0 = (r & 7) << 2;
        const float* X = x3 + ((size_t)b << 21);
        const float* Wb = g_Wt3 + b * 24576;
        for (int ch = 0; ch < 12; ch++) {
            int m = ch >> 1, c0 = (ch & 1) << 5;
            __syncthreads();
            const float4* ws = (const float4*)(Wb + ch * 2048);
#pragma unroll
            for (int it = 0; it < 2; it++) {
                int f = tid + it * 256;
                int o = f >> 3, k0 = (f & 7) << 2;
                *(float4*)(Ws + o * 32 + (k0 ^ (((o >> 2) & 7) << 2))) = ws[f];
            }
#pragma unroll
            for (int it = 0; it < 4; it++) {
                int idx = tid + it * 256;
                int row = idx >> 3, seg = idx & 7;
                int jj = row >> 5, k = row & 31, j = j0 + jj;
                int xr;
                switch (m) {
                    case 0:  xr = (i * 32 + j) * 32 + k; break;
                    case 1:  xr = (i * 32 + k) * 32 + j; break;
                    case 2:  xr = (j * 32 + i) * 32 + k; break;
                    case 3:  xr = (k * 32 + i) * 32 + j; break;
                    case 4:  xr = (j * 32 + k) * 32 + i; break;
                    default: xr = (k * 32 + j) * 32 + i; break;
                }
                *(float4*)(As + row * 32 + seg * 4) =
                    *(const float4*)(X + (size_t)xr * 64 + c0 + seg * 4);
            }
            __syncthreads();
            mm_chunk2(As, Ws, acc2, r0, tx);
        }
        int j = j0 + (ty >> 2), k0e = (ty & 3) * 8;
        int flag = g_flags[3];
        float4 p1 = *(const float4*)(g_P1 + (((b * 32 + i) * 32 + j) << 6) + tx * 4);
#pragma unroll
        for (int u = 0; u < 8; u++) {
            int k = k0e + u;
            float4 p2 = *(const float4*)(g_P2 + (((b * 32 + i) * 32 + k) << 6) + tx * 4);
            float4 p3 = *(const float4*)(g_P3 + (((b * 32 + j) * 32 + k) << 6) + tx * 4);
            F2U c0u, c1u, c2u, c3u;
            c0u.u = acc2[u][0]; c1u.u = acc2[u][1]; c2u.u = acc2[u][2]; c3u.u = acc2[u][3];
            float4 rO;
            rO.x = (c0u.f.x + c0u.f.y) + p1.x + p2.x + p3.x;
            rO.y = (c1u.f.x + c1u.f.y) + p1.y + p2.y + p3.y;
            rO.z = (c2u.f.x + c2u.f.y) + p1.z + p2.z + p3.z;
            rO.w = (c3u.f.x + c3u.f.y) + p1.w + p2.w + p3.w;
            if (flag) { rO.x = sigf(rO.x); rO.y = sigf(rO.y); rO.z = sigf(rO.z); rO.w = sigf(rO.w); }
            else      { rO.x = rO.y = rO.z = rO.w = 0.0f; }
            size_t oidx = O3_OFF + ((((size_t)(b * 32 + i) * 32 + j) * 32 + k) << 6) + tx * 4;
            *(float4*)(out + oidx) = rO;
        }
    } else {
        // ---- o2: block (b, i-quad) ----
        int bid2 = bid - 2048;
        int b = bid2 >> 3, i0 = (bid2 & 7) << 2;
        const float* Wb = g_Wt2 + (size_t)b * 32768;
        for (int ch = 0; ch < 16; ch++) {
            __syncthreads();
            const float4* ws = (const float4*)(Wb + ch * 2048);
#pragma unroll
            for (int it = 0; it < 2; it++) {
                int f = tid + it * 256;
                int o = f >> 3, k0 = (f & 7) << 2;
                *(float4*)(Ws + o * 32 + (k0 ^ (((o >> 2) & 7) << 2))) = ws[f];
            }
#pragma unroll
            for (int it = 0; it < 4; it++) {
                int idx = tid + it * 256;
                int row = idx >> 3, seg = idx & 7;
                int ii = row >> 5, j = row & 31, i = i0 + ii;
                int cp = ch * 32 + seg * 4;
                const float* src;
                if (cp < 64)       src = x1 + (b * 32 + i) * 64 + cp;
                else if (cp < 128) src = x1 + (b * 32 + j) * 64 + (cp - 64);
                else if (cp < 192) src = x2 + ((size_t)(b * 32 + i) * 32 + j) * 64 + (cp - 128);
                else if (cp < 256) src = x2 + ((size_t)(b * 32 + j) * 32 + i) * 64 + (cp - 192);
                else if (cp < 384) src = g_r3 + ((size_t)(b * 32 + i) * 32 + j) * 128 + (cp - 256);
                else               src = g_r3 + ((size_t)(b * 32 + j) * 32 + i) * 128 + (cp - 384);
                *(float4*)(As + row * 32 + seg * 4) = *(const float4*)src;
            }
            __syncthreads();
            mm_chunk2(As, Ws, acc2, r0, tx);
        }
        int i = i0 + (ty >> 2), j0k = (ty & 3) * 8;
        int flag = g_flags[2];
        float4 bs = *(const float4*)(g_bias2 + b * 64 + tx * 4);
#pragma unroll
        for (int u = 0; u < 8; u++) {
            int j = j0k + u;
            F2U c0u, c1u, c2u, c3u;
            c0u.u = acc2[u][0]; c1u.u = acc2[u][1]; c2u.u = acc2[u][2]; c3u.u = acc2[u][3];
            float4 rO;
            rO.x = (c0u.f.x + c0u.f.y) + bs.x;
            rO.y = (c1u.f.x + c1u.f.y) + bs.y;
            rO.z = (c2u.f.x + c2u.f.y) + bs.z;
            rO.w = (c3u.f.x + c3u.f.y) + bs.w;
            if (flag) { rO.x = sigf(rO.x); rO.y = sigf(rO.y); rO.z = sigf(rO.z); rO.w = sigf(rO.w); }
            else      { rO.x = rO.y = rO.z = rO.w = 0.0f; }
            size_t oidx = O2_OFF + (((size_t)(b * 32 + i) * 32 + j) << 6) + tx * 4;
            *(float4*)(out + oidx) = rO;
        }
    }
}

// ------------------------------- launch -------------------------------------
extern "C" void kernel_launch(void* const* d_in, const int* in_sizes, int n_in,
                              void* d_out, int out_size) {
    const float* x0 = (const float*)d_in[0];
    const float* x1 = (const float*)d_in[1];
    const float* x2 = (const float*)d_in[2];
    const float* x3 = (const float*)d_in[3];
    const float* w_op0 = (const float*)d_in[4];
    const float* b_op0 = (const float*)d_in[5];
    const float* w_red0 = (const float*)d_in[6];
    const float* b_red0 = (const float*)d_in[7];
    const float* w_exp1 = (const float*)d_in[8];
    const float* b_exp1 = (const float*)d_in[9];
    const float* w_op1 = (const float*)d_in[10];
    const float* b_op1 = (const float*)d_in[11];
    const float* w_red1 = (const float*)d_in[12];
    const float* b_red1 = (const float*)d_in[13];
    const float* w_exp2 = (const float*)d_in[14];
    const float* b_exp2 = (const float*)d_in[15];
    const float* w_op2 = (const float*)d_in[16];
    const float* b_op2 = (const float*)d_in[17];
    const float* w_red2 = (const float*)d_in[18];
    const float* b_red2 = (const float*)d_in[19];
    const float* w_exp3 = (const float*)d_in[20];
    const float* b_exp3 = (const float*)d_in[21];
    const float* w_op3 = (const float*)d_in[22];
    const float* b_op3 = (const float*)d_in[23];
    const int* act = (const int*)d_in[24];
    float* out = (float*)d_out;

    prep_kernel<<<64, 256>>>(w_exp3, w_op3, w_exp2, w_op2, w_red2,
                             b_exp3, b_op3, b_exp2, b_op2, b_red2, act);
    reduce1_kernel<<<8, 64>>>(x1);
    reduce2_kernel<<<256, 64>>>(x2);
    reduce3_kernel<<<8192, 64>>>(x3);
    y2_kernel<<<256, 384>>>(x2);
    psum_kernel<<<2048, 256>>>();
    o0_kernel<<<8, 64>>>(x0, w_op0, b_op0, w_red0, b_red0, out);
    o1_kernel<<<256, 64>>>(x0, x1, w_exp1, b_exp1, w_op1, b_op1, w_red1, b_red1, out);
    main_kernel<<<2112, 256>>>(x1, x2, x3, out);
}

// round 6
// speedup vs baseline: 1.4606x; 1.3367x over previous
#include <cuda_runtime.h>
#include <math.h>
#include <stdint.h>

// B=8, n=32, C=64, O=64
// out: concat(o0[8,64], o1[8,32,64], o2[8,32,32,64], o3[8,32,32,32,64]) f32

#define O1_OFF 512
#define O2_OFF 16896
#define O3_OFF 541184

// ---------------- device scratch ----------------
__device__ __align__(16) float g_We3T[384 * 64];
__device__ __align__(16) float g_Wt3[8 * 12 * 2048];   // [b][chunk][frag-order], tf32
__device__ __align__(16) float g_Wt2[8 * 16 * 2048];   // [b][chunk][frag-order], tf32
__device__ __align__(16) float g_bias3[8 * 64];
__device__ __align__(16) float g_bias2[8 * 64];
__device__ __align__(16) float g_scal[8 * 10];
__device__ int g_flags[4];
__device__ __align__(16) float g_r1[8 * 128];
__device__ __align__(16) float g_r2[8 * 32 * 128];
__device__ __align__(16) float g_r3[8 * 32 * 32 * 128];
__device__ __align__(16) float g_y2[8 * 32 * 32 * 384];
__device__ __align__(16) float g_P1[8 * 32 * 32 * 64];
__device__ __align__(16) float g_P2[8 * 32 * 32 * 64];
__device__ __align__(16) float g_P3[8 * 32 * 32 * 64];

__device__ __forceinline__ float sigf(float x) { return 1.0f / (1.0f + __expf(-x)); }

__device__ __forceinline__ float to_tf32(float x) {
    uint32_t u;
    asm("cvt.rna.tf32.f32 %0, %1;" : "=r"(u) : "f"(x));
    return __uint_as_float(u);
}

// m16n8k8 tf32 mma: D += A * B^T  (A 16x8 row-major frag, B given as [n][k])
__device__ __forceinline__ void mma1688(float* d, const uint32_t* a, const uint32_t* b) {
    asm volatile(
        "mma.sync.aligned.m16n8k8.row.col.f32.tf32.tf32.f32 "
        "{%0,%1,%2,%3}, {%4,%5,%6,%7}, {%8,%9}, {%0,%1,%2,%3};"
        : "+f"(d[0]), "+f"(d[1]), "+f"(d[2]), "+f"(d[3])
        : "r"(a[0]), "r"(a[1]), "r"(a[2]), "r"(a[3]), "r"(b[0]), "r"(b[1]));
}

// ------------------------------- prep -------------------------------------
// Wt3/Wt2 emitted in per-chunk B-fragment order:
//   pos = ((nt*4+ks)*32 + lane)*2 + comp
//   o = nt*8 + (lane>>2),  k = ks*8 + (lane&3) + comp*4
__global__ void prep_kernel(const float* __restrict__ w_exp3, const float* __restrict__ w_op3,
                            const float* __restrict__ w_exp2, const float* __restrict__ w_op2,
                            const float* __restrict__ w_red2, const float* __restrict__ b_exp3,
                            const float* __restrict__ b_op3, const float* __restrict__ b_exp2,
                            const float* __restrict__ b_op2, const float* __restrict__ b_red2,
                            const int* __restrict__ act) {
    int t = blockIdx.x * blockDim.x + threadIdx.x;
    int nth = gridDim.x * blockDim.x;
    if (t < 80) g_scal[t] = (float)act[t];
    if (t == 0) {
        int f0 = 0, f1 = 0, f2 = 0, f3 = 0;
        for (int b = 0; b < 8; b++) {
            f0 |= act[b * 10 + 0] | act[b * 10 + 1];
            f1 |= act[b * 10 + 2] | act[b * 10 + 3] | act[b * 10 + 4];
            f2 |= act[b * 10 + 5] | act[b * 10 + 6] | act[b * 10 + 7];
            f3 |= act[b * 10 + 8] | act[b * 10 + 9];
        }
        g_flags[0] = f0; g_flags[1] = f1; g_flags[2] = f2; g_flags[3] = f3;
    }
    for (int f = t; f < 24576; f += nth) {          // We3T[c*384 + m*64 + o] (fp32, y2)
        int o = f / 384, r = f % 384, m = r >> 6, c = r & 63;
        g_We3T[c * 384 + m * 64 + o] = w_exp3[f];
    }
    for (int f = t; f < 8 * 24576; f += nth) {
        int b = f / 24576, r = f % 24576;
        int ch = r >> 11, pos = r & 2047;
        int ntks = pos >> 6, lane = (pos >> 1) & 31, comp = pos & 1;
        int o = (ntks >> 2) * 8 + (lane >> 2);
        int k = (ntks & 3) * 8 + (lane & 3) + comp * 4;
        g_Wt3[f] = to_tf32((float)act[b * 10 + 9] * w_op3[o * 384 + ch * 32 + k]);
    }
    for (int f = t; f < 8 * 32768; f += nth) {
        int b = f >> 15, r = f & 32767;
        int ch = r >> 11, pos = r & 2047;
        int ntks = pos >> 6, lane = (pos >> 1) & 31, comp = pos & 1;
        int o = (ntks >> 2) * 8 + (lane >> 2);
        int k = (ntks & 3) * 8 + (lane & 3) + comp * 4;
        int cp = ch * 32 + k;
        float v;
        if (cp < 128)      v = (float)act[b * 10 + 5] * w_exp2[o * 128 + cp];
        else if (cp < 256) v = (float)act[b * 10 + 6] * w_op2[o * 128 + (cp - 128)];
        else               v = (float)act[b * 10 + 7] * w_red2[o * 256 + (cp - 256)];
        g_Wt2[f] = to_tf32(v);
    }
    for (int f = t; f < 512; f += nth) {
        int b = f >> 6, o = f & 63;
        g_bias3[f] = (float)act[b * 10 + 8] * b_exp3[o] + (float)act[b * 10 + 9] * b_op3[o];
        g_bias2[f] = (float)act[b * 10 + 5] * b_exp2[o] + (float)act[b * 10 + 6] * b_op2[o]
                   + (float)act[b * 10 + 7] * b_red2[o];
    }
}

// ----------------------------- reductions ----------------------------------
__global__ void reduce1_kernel(const float* __restrict__ x1) {
    int b = blockIdx.x, c = threadIdx.x;
    float ex = -INFINITY, fa = INFINITY;
    for (int i = 0; i < 32; i++) {
        float v = x1[(b * 32 + i) * 64 + c];
        ex = fmaxf(ex, v); fa = fminf(fa, v);
    }
    g_r1[b * 128 + 2 * c] = ex;
    g_r1[b * 128 + 2 * c + 1] = fa;
}

__global__ void reduce2_kernel(const float* __restrict__ x2) {
    int blk = blockIdx.x;
    int c = threadIdx.x;
    int i = blk & 31;
    const float* base = x2 + (size_t)blk * 2048;
    float ex = 0.0f, fa = 1.0f;
    for (int j = 0; j < 32; j++) {
        if (j == i) continue;
        float v = base[j * 64 + c];
        ex = fmaxf(ex, v); fa = fminf(fa, v);
    }
    g_r2[blk * 128 + 2 * c] = ex;
    g_r2[blk * 128 + 2 * c + 1] = fa;
}

__global__ void __launch_bounds__(128) reduce3_kernel(const float* __restrict__ x3) {
    int sub = threadIdx.x >> 5;
    int c2 = threadIdx.x & 31;
    int blk = blockIdx.x * 4 + sub;             // b*1024 + i*32 + j
    int i = (blk >> 5) & 31, j = blk & 31;
    float ex0 = 0.0f, fa0 = 1.0f, ex1 = 0.0f, fa1 = 1.0f;
    float ex0b = 0.0f, fa0b = 1.0f, ex1b = 0.0f, fa1b = 1.0f;
    if (i != j) {
        const float2* base = (const float2*)(x3 + (size_t)blk * 2048) + c2;
#pragma unroll 4
        for (int k = 0; k < 32; k += 2) {
            float2 v0 = base[k * 32];
            float2 v1 = base[(k + 1) * 32];
            if (k != i && k != j) {
                ex0 = fmaxf(ex0, v0.x); fa0 = fminf(fa0, v0.x);
                ex0b = fmaxf(ex0b, v0.y); fa0b = fminf(fa0b, v0.y);
            }
            if (k + 1 != i && k + 1 != j) {
                ex1 = fmaxf(ex1, v1.x); fa1 = fminf(fa1, v1.x);
                ex1b = fmaxf(ex1b, v1.y); fa1b = fminf(fa1b, v1.y);
            }
        }
    }
    float4 r;
    r.x = fmaxf(ex0, ex1); r.y = fminf(fa0, fa1);
    r.z = fmaxf(ex0b, ex1b); r.w = fminf(fa0b, fa1b);
    if (i == j) { r.x = 0.0f; r.y = 1.0f; r.z = 0.0f; r.w = 1.0f; }
    *(float4*)(g_r3 + (size_t)blk * 128 + 4 * c2) = r;
}

// ------------- y2[b,p,q, m*64+o] = sum_c x2[b,p,q,c] * w_exp3[o, m*64+c] ----
__global__ void __launch_bounds__(384) y2_kernel(const float* __restrict__ x2) {
    __shared__ float Ash[2048];
    __shared__ float Wsh[16 * 384];
    int tid = threadIdx.x;
    int blk = blockIdx.x;
    for (int f = tid; f < 2048; f += 384) Ash[f] = x2[(size_t)blk * 2048 + f];
    float acc[32];
#pragma unroll
    for (int q = 0; q < 32; q++) acc[q] = 0.0f;
    for (int cc = 0; cc < 4; cc++) {
        __syncthreads();
#pragma unroll
        for (int it = 0; it < 16; it++)
            Wsh[it * 384 + tid] = g_We3T[cc * 6144 + it * 384 + tid];
        __syncthreads();
#pragma unroll
        for (int q = 0; q < 32; q++) {
            float s = acc[q];
#pragma unroll
            for (int c2 = 0; c2 < 16; c2++)
                s = fmaf(Ash[q * 64 + cc * 16 + c2], Wsh[c2 * 384 + tid], s);
            acc[q] = s;
        }
    }
#pragma unroll
    for (int q = 0; q < 32; q++)
        g_y2[((size_t)blk * 32 + q) * 384 + tid] = acc[q];
}

// ----------------- pair sums P1/P2/P3 (a8 + bias folded) --------------------
__global__ void psum_kernel() {
    int t = blockIdx.x * blockDim.x + threadIdx.x;
    int o = t & 63, q = (t >> 6) & 31, p = (t >> 11) & 31, b = t >> 16;
    float a8 = g_scal[b * 10 + 8];
    size_t pq = ((size_t)(b * 32 + p) * 32 + q) * 384;
    size_t qp = ((size_t)(b * 32 + q) * 32 + p) * 384;
    g_P1[t] = a8 * (g_y2[pq + o] + g_y2[qp + 128 + o]) + g_bias3[b * 64 + o];
    g_P2[t] = a8 * (g_y2[pq + 64 + o] + g_y2[qp + 192 + o]);
    g_P3[t] = a8 * (g_y2[pq + 256 + o] + g_y2[qp + 320 + o]);
}

// ------------------------------- o0 / o1 -----------------------------------
__global__ void o0_kernel(const float* __restrict__ x0,
                          const float* __restrict__ w_op0, const float* __restrict__ b_op0,
                          const float* __restrict__ w_red0, const float* __restrict__ b_red0,
                          float* __restrict__ out) {
    int b = blockIdx.x, o = threadIdx.x;
    __shared__ float xs[64], rs[128];
    xs[o] = x0[b * 64 + o];
    rs[o] = g_r1[b * 128 + o];
    rs[o + 64] = g_r1[b * 128 + 64 + o];
    __syncthreads();
    float d0 = 0.0f, d1 = 0.0f;
#pragma unroll 8
    for (int c = 0; c < 64; c++) d0 = fmaf(w_op0[o * 64 + c], xs[c], d0);
#pragma unroll 8
    for (int c = 0; c < 128; c++) d1 = fmaf(w_red0[o * 128 + c], rs[c], d1);
    float s = g_scal[b * 10 + 0] * (d0 + b_op0[o]) + g_scal[b * 10 + 1] * (d1 + b_red0[o]);
    out[b * 64 + o] = g_flags[0] ? sigf(s) : 0.0f;
}

__global__ void o1_kernel(const float* __restrict__ x0, const float* __restrict__ x1,
                          const float* __restrict__ w_exp1, const float* __restrict__ b_exp1,
                          const float* __restrict__ w_op1, const float* __restrict__ b_op1,
                          const float* __restrict__ w_red1, const float* __restrict__ b_red1,
                          float* __restrict__ out) {
    int blk = blockIdx.x;
    int b = blk >> 5, o = threadIdx.x;
    __shared__ float x0s[64], x1s[64], r2s[128];
    x0s[o] = x0[b * 64 + o];
    x1s[o] = x1[blk * 64 + o];
    r2s[o] = g_r2[blk * 128 + o];
    r2s[o + 64] = g_r2[blk * 128 + 64 + o];
    __syncthreads();
    float d0 = 0.0f, d1 = 0.0f, d2 = 0.0f;
#pragma unroll 8
    for (int c = 0; c < 64; c++) {
        d0 = fmaf(w_exp1[o * 64 + c], x0s[c], d0);
        d1 = fmaf(w_op1[o * 64 + c], x1s[c], d1);
    }
#pragma unroll 8
    for (int c = 0; c < 128; c++) d2 = fmaf(w_red1[o * 128 + c], r2s[c], d2);
    float s = g_scal[b * 10 + 2] * (d0 + b_exp1[o]) + g_scal[b * 10 + 3] * (d1 + b_op1[o])
            + g_scal[b * 10 + 4] * (d2 + b_red1[o]);
    out[O1_OFF + blk * 64 + o] = g_flags[1] ? sigf(s) : 0.0f;
}

// ----------------- shared gather->fragment scatter helper --------------------
// A-frag layout: As[((warp*4+ks)*32 + lane)*4 + comp]
//   element (row,k): warp=row>>4, g=row&7, hi=(row>>3)&1, ks=k>>3, c=k&3 (within
//   half), ch2=(k>>2)&1, lane=g*4+c, comp=hi+2*ch2
__device__ __forceinline__ void scatter_Afrag(float* As, int row, int seg, float4 v) {
    int warp = row >> 4, rl = row & 15, g = rl & 7, hi = rl >> 3;
    int ks = seg >> 1, ch2 = seg & 1;
    int comp = hi + 2 * ch2;
    int base = ((warp * 4 + ks) * 32 + g * 4) * 4 + comp;
    As[base] = to_tf32(v.x);
    As[base + 4] = to_tf32(v.y);
    As[base + 8] = to_tf32(v.z);
    As[base + 12] = to_tf32(v.w);
}

// ------------------------ o3 via mma.sync tf32 -------------------------------
__global__ void __launch_bounds__(256) o3t_kernel(const float* __restrict__ x3,
                                                  float* __restrict__ out) {
    __shared__ float As[4096];   // A fragments, 128x32
    __shared__ float Ws[2048];   // B fragments, 64x32 (chunk, frag order)
    int tid = threadIdx.x, wid = tid >> 5, lane = tid & 31;
    int bid = blockIdx.x;
    int b = bid >> 8, r = bid & 255, i = r >> 3, j0 = (r & 7) << 2;
    const float* X = x3 + ((size_t)b << 21);
    const float* Wb = g_Wt3 + b * 24576;

    float acc[8][4];
#pragma unroll
    for (int nt = 0; nt < 8; nt++)
#pragma unroll
        for (int v = 0; v < 4; v++) acc[nt][v] = 0.0f;

    for (int ch = 0; ch < 12; ch++) {
        int m = ch >> 1, c0 = (ch & 1) << 5;
        __syncthreads();
        const float4* ws = (const float4*)(Wb + ch * 2048);
        ((float4*)Ws)[tid] = ws[tid];
        ((float4*)Ws)[tid + 256] = ws[tid + 256];
#pragma unroll
        for (int it = 0; it < 4; it++) {
            int idx = tid + it * 256;
            int row = idx >> 3, seg = idx & 7;
            int jj = row >> 5, k = row & 31, j = j0 + jj;
            int xr;
            switch (m) {
                case 0:  xr = (i * 32 + j) * 32 + k; break;
                case 1:  xr = (i * 32 + k) * 32 + j; break;
                case 2:  xr = (j * 32 + i) * 32 + k; break;
                case 3:  xr = (k * 32 + i) * 32 + j; break;
                case 4:  xr = (j * 32 + k) * 32 + i; break;
                default: xr = (k * 32 + j) * 32 + i; break;
            }
            float4 v = *(const float4*)(X + (size_t)xr * 64 + c0 + seg * 4);
            scatter_Afrag(As, row, seg, v);
        }
        __syncthreads();
#pragma unroll
        for (int ks = 0; ks < 4; ks++) {
            uint4 au = *(const uint4*)(As + ((wid * 4 + ks) * 32 + lane) * 4);
            uint32_t a[4] = {au.x, au.y, au.z, au.w};
#pragma unroll
            for (int nt = 0; nt < 8; nt++) {
                uint2 bu = *(const uint2*)(Ws + ((nt * 4 + ks) * 32 + lane) * 2);
                uint32_t bf[2] = {bu.x, bu.y};
                mma1688(acc[nt], a, bf);
            }
        }
    }

    // epilogue
    int flag = g_flags[3];
    int g = lane >> 2, c2 = (lane & 3) * 2;
#pragma unroll
    for (int hi = 0; hi < 2; hi++) {
        int row = wid * 16 + g + 8 * hi;
        int jj = row >> 5, kk = row & 31, j = j0 + jj;
        const float* p1p = g_P1 + (((b * 32 + i) * 32 + j) << 6);
        const float* p2p = g_P2 + (((b * 32 + i) * 32 + kk) << 6);
        const float* p3p = g_P3 + (((b * 32 + j) * 32 + kk) << 6);
        float* op = out + O3_OFF + ((((size_t)(b * 32 + i) * 32 + j) * 32 + kk) << 6);
#pragma unroll
        for (int nt = 0; nt < 8; nt++) {
            int col = nt * 8 + c2;
            float2 p1 = *(const float2*)(p1p + col);
            float2 p2 = *(const float2*)(p2p + col);
            float2 p3 = *(const float2*)(p3p + col);
            float v0 = acc[nt][hi * 2] + p1.x + p2.x + p3.x;
            float v1 = acc[nt][hi * 2 + 1] + p1.y + p2.y + p3.y;
            if (flag) { v0 = sigf(v0); v1 = sigf(v1); }
            else      { v0 = 0.0f; v1 = 0.0f; }
            float2 rr; rr.x = v0; rr.y = v1;
            *(float2*)(op + col) = rr;
        }
    }
}

// ------------------------ o2 via mma.sync tf32 -------------------------------
__global__ void __launch_bounds__(256) o2t_kernel(const float* __restrict__ x1,
                                                  const float* __restrict__ x2,
                                                  float* __restrict__ out) {
    __shared__ float As[4096];
    __shared__ float Ws[2048];
    int tid = threadIdx.x, wid = tid >> 5, lane = tid & 31;
    int bid = blockIdx.x;
    int b = bid >> 3, i0 = (bid & 7) << 2;
    const float* Wb = g_Wt2 + (size_t)b * 32768;

    float acc[8][4];
#pragma unroll
    for (int nt = 0; nt < 8; nt++)
#pragma unroll
        for (int v = 0; v < 4; v++) acc[nt][v] = 0.0f;

    for (int ch = 0; ch < 16; ch++) {
        __syncthreads();
        const float4* ws = (const float4*)(Wb + ch * 2048);
        ((float4*)Ws)[tid] = ws[tid];
        ((float4*)Ws)[tid + 256] = ws[tid + 256];
#pragma unroll
        for (int it = 0; it < 4; it++) {
            int idx = tid + it * 256;
            int row = idx >> 3, seg = idx & 7;
            int ii = row >> 5, j = row & 31, i = i0 + ii;
            int cp = ch * 32 + seg * 4;
            const float* src;
            if (cp < 64)       src = x1 + (b * 32 + i) * 64 + cp;
            else if (cp < 128) src = x1 + (b * 32 + j) * 64 + (cp - 64);
            else if (cp < 192) src = x2 + ((size_t)(b * 32 + i) * 32 + j) * 64 + (cp - 128);
            else if (cp < 256) src = x2 + ((size_t)(b * 32 + j) * 32 + i) * 64 + (cp - 192);
            else if (cp < 384) src = g_r3 + ((size_t)(b * 32 + i) * 32 + j) * 128 + (cp - 256);
            else               src = g_r3 + ((size_t)(b * 32 + j) * 32 + i) * 128 + (cp - 384);
            float4 v = *(const float4*)src;
            scatter_Afrag(As, row, seg, v);
        }
        __syncthreads();
#pragma unroll
        for (int ks = 0; ks < 4; ks++) {
            uint4 au = *(const uint4*)(As + ((wid * 4 + ks) * 32 + lane) * 4);
            uint32_t a[4] = {au.x, au.y, au.z, au.w};
#pragma unroll
            for (int nt = 0; nt < 8; nt++) {
                uint2 bu = *(const uint2*)(Ws + ((nt * 4 + ks) * 32 + lane) * 2);
                uint32_t bf[2] = {bu.x, bu.y};
                mma1688(acc[nt], a, bf);
            }
        }
    }

    int flag = g_flags[2];
    int g = lane >> 2, c2 = (lane & 3) * 2;
#pragma unroll
    for (int hi = 0; hi < 2; hi++) {
        int row = wid * 16 + g + 8 * hi;
        int ii = row >> 5, j = row & 31, i = i0 + ii;
        const float* bsp = g_bias2 + b * 64;
        float* op = out + O2_OFF + (((size_t)(b * 32 + i) * 32 + j) << 6);
#pragma unroll
        for (int nt = 0; nt < 8; nt++) {
            int col = nt * 8 + c2;
            float2 bs = *(const float2*)(bsp + col);
            float v0 = acc[nt][hi * 2] + bs.x;
            float v1 = acc[nt][hi * 2 + 1] + bs.y;
            if (flag) { v0 = sigf(v0); v1 = sigf(v1); }
            else      { v0 = 0.0f; v1 = 0.0f; }
            float2 rr; rr.x = v0; rr.y = v1;
            *(float2*)(op + col) = rr;
        }
    }
}

// ------------------------------- launch -------------------------------------
extern "C" void kernel_launch(void* const* d_in, const int* in_sizes, int n_in,
                              void* d_out, int out_size) {
    const float* x0 = (const float*)d_in[0];
    const float* x1 = (const float*)d_in[1];
    const float* x2 = (const float*)d_in[2];
    const float* x3 = (const float*)d_in[3];
    const float* w_op0 = (const float*)d_in[4];
    const float* b_op0 = (const float*)d_in[5];
    const float* w_red0 = (const float*)d_in[6];
    const float* b_red0 = (const float*)d_in[7];
    const float* w_exp1 = (const float*)d_in[8];
    const float* b_exp1 = (const float*)d_in[9];
    const float* w_op1 = (const float*)d_in[10];
    const float* b_op1 = (const float*)d_in[11];
    const float* w_red1 = (const float*)d_in[12];
    const float* b_red1 = (const float*)d_in[13];
    const float* w_exp2 = (const float*)d_in[14];
    const float* b_exp2 = (const float*)d_in[15];
    const float* w_op2 = (const float*)d_in[16];
    const float* b_op2 = (const float*)d_in[17];
    const float* w_red2 = (const float*)d_in[18];
    const float* b_red2 = (const float*)d_in[19];
    const float* w_exp3 = (const float*)d_in[20];
    const float* b_exp3 = (const float*)d_in[21];
    const float* w_op3 = (const float*)d_in[22];
    const float* b_op3 = (const float*)d_in[23];
    const int* act = (const int*)d_in[24];
    float* out = (float*)d_out;

    prep_kernel<<<64, 256>>>(w_exp3, w_op3, w_exp2, w_op2, w_red2,
                             b_exp3, b_op3, b_exp2, b_op2, b_red2, act);
    y2_kernel<<<256, 384>>>(x2);
    psum_kernel<<<2048, 256>>>();
    o3t_kernel<<<2048, 256>>>(x3, out);
    reduce3_kernel<<<2048, 128>>>(x3);
    o2t_kernel<<<64, 256>>>(x1, x2, out);
    reduce2_kernel<<<256, 64>>>(x2);
    reduce1_kernel<<<8, 64>>>(x1);
    o0_kernel<<<8, 64>>>(x0, w_op0, b_op0, w_red0, b_red0, out);
    o1_kernel<<<256, 64>>>(x0, x1, w_exp1, b_exp1, w_op1, b_op1, w_red1, b_red1, out);
}

// round 7
// speedup vs baseline: 1.8029x; 1.2343x over previous
#include <cuda_runtime.h>
#include <math.h>
#include <stdint.h>

// B=8, n=32, C=64, O=64
// out: concat(o0[8,64], o1[8,32,64], o2[8,32,32,64], o3[8,32,32,32,64]) f32

#define O1_OFF 512
#define O2_OFF 16896
#define O3_OFF 541184

// ---------------- device scratch ----------------
__device__ __align__(16) float g_We3T[384 * 64];
__device__ __align__(16) float g_Wt3[8 * 12 * 2048];   // [b][chunk][frag-order], tf32
__device__ __align__(16) float g_Wt2[8 * 16 * 2048];   // [b][chunk][frag-order], tf32
__device__ __align__(16) float g_bias3[8 * 64];
__device__ __align__(16) float g_bias2[8 * 64];
__device__ __align__(16) float g_scal[8 * 10];
__device__ int g_flags[4];
__device__ __align__(16) float g_r3[8 * 32 * 32 * 128];
__device__ __align__(16) float g_y2[8 * 32 * 32 * 384];
__device__ __align__(16) float g_P1[8 * 32 * 32 * 64];
__device__ __align__(16) float g_P2[8 * 32 * 32 * 64];
__device__ __align__(16) float g_P3[8 * 32 * 32 * 64];

__device__ __forceinline__ float sigf(float x) { return 1.0f / (1.0f + __expf(-x)); }

__device__ __forceinline__ float to_tf32(float x) {
    uint32_t u;
    asm("cvt.rna.tf32.f32 %0, %1;" : "=r"(u) : "f"(x));
    return __uint_as_float(u);
}

// m16n8k8 tf32 mma: D += A * B^T
__device__ __forceinline__ void mma1688(float* d, const uint32_t* a, const uint32_t* b) {
    asm volatile(
        "mma.sync.aligned.m16n8k8.row.col.f32.tf32.tf32.f32 "
        "{%0,%1,%2,%3}, {%4,%5,%6,%7}, {%8,%9}, {%0,%1,%2,%3};"
        : "+f"(d[0]), "+f"(d[1]), "+f"(d[2]), "+f"(d[3])
        : "r"(a[0]), "r"(a[1]), "r"(a[2]), "r"(a[3]), "r"(b[0]), "r"(b[1]));
}

// A-frag smem layout: slot = tile*4 + ks (tile = row>>4), pitch 132 floats.
// addr_f = slot*132 + lane*4 + comp;  reader: LDS.128 -> {comp0..3}.
#define SLOT_PITCH 132

// ------------------------------- prep -------------------------------------
// Wt3/Wt2 in per-chunk B-fragment order:
//   pos = ((nt*4+ks)*32 + lane)*2 + comp; o = nt*8+(lane>>2); k = ks*8+(lane&3)+comp*4
__global__ void prep_kernel(const float* __restrict__ w_exp3, const float* __restrict__ w_op3,
                            const float* __restrict__ w_exp2, const float* __restrict__ w_op2,
                            const float* __restrict__ w_red2, const float* __restrict__ b_exp3,
                            const float* __restrict__ b_op3, const float* __restrict__ b_exp2,
                            const float* __restrict__ b_op2, const float* __restrict__ b_red2,
                            const int* __restrict__ act) {
    int t = blockIdx.x * blockDim.x + threadIdx.x;
    int nth = gridDim.x * blockDim.x;
    if (t < 80) g_scal[t] = (float)act[t];
    if (t == 0) {
        int f0 = 0, f1 = 0, f2 = 0, f3 = 0;
        for (int b = 0; b < 8; b++) {
            f0 |= act[b * 10 + 0] | act[b * 10 + 1];
            f1 |= act[b * 10 + 2] | act[b * 10 + 3] | act[b * 10 + 4];
            f2 |= act[b * 10 + 5] | act[b * 10 + 6] | act[b * 10 + 7];
            f3 |= act[b * 10 + 8] | act[b * 10 + 9];
        }
        g_flags[0] = f0; g_flags[1] = f1; g_flags[2] = f2; g_flags[3] = f3;
    }
    for (int f = t; f < 24576; f += nth) {          // We3T[c*384 + m*64 + o]
        int o = f / 384, r = f % 384, m = r >> 6, c = r & 63;
        g_We3T[c * 384 + m * 64 + o] = w_exp3[f];
    }
    for (int f = t; f < 8 * 24576; f += nth) {
        int b = f / 24576, r = f % 24576;
        int ch = r >> 11, pos = r & 2047;
        int ntks = pos >> 6, lane = (pos >> 1) & 31, comp = pos & 1;
        int o = (ntks >> 2) * 8 + (lane >> 2);
        int k = (ntks & 3) * 8 + (lane & 3) + comp * 4;
        g_Wt3[f] = to_tf32((float)act[b * 10 + 9] * w_op3[o * 384 + ch * 32 + k]);
    }
    for (int f = t; f < 8 * 32768; f += nth) {
        int b = f >> 15, r = f & 32767;
        int ch = r >> 11, pos = r & 2047;
        int ntks = pos >> 6, lane = (pos >> 1) & 31, comp = pos & 1;
        int o = (ntks >> 2) * 8 + (lane >> 2);
        int k = (ntks & 3) * 8 + (lane & 3) + comp * 4;
        int cp = ch * 32 + k;
        float v;
        if (cp < 128)      v = (float)act[b * 10 + 5] * w_exp2[o * 128 + cp];
        else if (cp < 256) v = (float)act[b * 10 + 6] * w_op2[o * 128 + (cp - 128)];
        else               v = (float)act[b * 10 + 7] * w_red2[o * 256 + (cp - 256)];
        g_Wt2[f] = to_tf32(v);
    }
    for (int f = t; f < 512; f += nth) {
        int b = f >> 6, o = f & 63;
        g_bias3[f] = (float)act[b * 10 + 8] * b_exp3[o] + (float)act[b * 10 + 9] * b_op3[o];
        g_bias2[f] = (float)act[b * 10 + 5] * b_exp2[o] + (float)act[b * 10 + 6] * b_op2[o]
                   + (float)act[b * 10 + 7] * b_red2[o];
    }
}

// ----------------------------- reduce3 ----------------------------------
__global__ void __launch_bounds__(128) reduce3_kernel(const float* __restrict__ x3) {
    int sub = threadIdx.x >> 5;
    int c2 = threadIdx.x & 31;
    int blk = blockIdx.x * 4 + sub;             // b*1024 + i*32 + j
    int i = (blk >> 5) & 31, j = blk & 31;
    float ex0 = 0.0f, fa0 = 1.0f, ex1 = 0.0f, fa1 = 1.0f;
    float ex0b = 0.0f, fa0b = 1.0f, ex1b = 0.0f, fa1b = 1.0f;
    if (i != j) {
        const float2* base = (const float2*)(x3 + (size_t)blk * 2048) + c2;
#pragma unroll 4
        for (int k = 0; k < 32; k += 2) {
            float2 v0 = base[k * 32];
            float2 v1 = base[(k + 1) * 32];
            if (k != i && k != j) {
                ex0 = fmaxf(ex0, v0.x); fa0 = fminf(fa0, v0.x);
                ex0b = fmaxf(ex0b, v0.y); fa0b = fminf(fa0b, v0.y);
            }
            if (k + 1 != i && k + 1 != j) {
                ex1 = fmaxf(ex1, v1.x); fa1 = fminf(fa1, v1.x);
                ex1b = fmaxf(ex1b, v1.y); fa1b = fminf(fa1b, v1.y);
            }
        }
    }
    float4 r;
    r.x = fmaxf(ex0, ex1); r.y = fminf(fa0, fa1);
    r.z = fmaxf(ex0b, ex1b); r.w = fminf(fa0b, fa1b);
    if (i == j) { r.x = 0.0f; r.y = 1.0f; r.z = 0.0f; r.w = 1.0f; }
    *(float4*)(g_r3 + (size_t)blk * 128 + 4 * c2) = r;
}

// ------------- y2[b,p,q, m*64+o] = sum_c x2[b,p,q,c] * w_exp3[o, m*64+c] ----
__global__ void __launch_bounds__(384) y2_kernel(const float* __restrict__ x2) {
    __shared__ float Ash[2048];
    __shared__ float Wsh[16 * 384];
    int tid = threadIdx.x;
    int blk = blockIdx.x;
    for (int f = tid; f < 2048; f += 384) Ash[f] = x2[(size_t)blk * 2048 + f];
    float acc[32];
#pragma unroll
    for (int q = 0; q < 32; q++) acc[q] = 0.0f;
    for (int cc = 0; cc < 4; cc++) {
        __syncthreads();
#pragma unroll
        for (int it = 0; it < 16; it++)
            Wsh[it * 384 + tid] = g_We3T[cc * 6144 + it * 384 + tid];
        __syncthreads();
#pragma unroll
        for (int q = 0; q < 32; q++) {
            float s = acc[q];
#pragma unroll
            for (int c2 = 0; c2 < 16; c2++)
                s = fmaf(Ash[q * 64 + cc * 16 + c2], Wsh[c2 * 384 + tid], s);
            acc[q] = s;
        }
    }
#pragma unroll
    for (int q = 0; q < 32; q++)
        g_y2[((size_t)blk * 32 + q) * 384 + tid] = acc[q];
}

// ----------------- pair sums P1/P2/P3 (a8 + bias folded) --------------------
__global__ void psum_kernel() {
    int t = blockIdx.x * blockDim.x + threadIdx.x;
    int o = t & 63, q = (t >> 6) & 31, p = (t >> 11) & 31, b = t >> 16;
    float a8 = g_scal[b * 10 + 8];
    size_t pq = ((size_t)(b * 32 + p) * 32 + q) * 384;
    size_t qp = ((size_t)(b * 32 + q) * 32 + p) * 384;
    g_P1[t] = a8 * (g_y2[pq + o] + g_y2[qp + 128 + o]) + g_bias3[b * 64 + o];
    g_P2[t] = a8 * (g_y2[pq + 64 + o] + g_y2[qp + 192 + o]);
    g_P3[t] = a8 * (g_y2[pq + 256 + o] + g_y2[qp + 320 + o]);
}

// ------------------------------- o0 / o1 (reductions fused) -----------------
__global__ void o0_kernel(const float* __restrict__ x0, const float* __restrict__ x1,
                          const float* __restrict__ w_op0, const float* __restrict__ b_op0,
                          const float* __restrict__ w_red0, const float* __restrict__ b_red0,
                          float* __restrict__ out) {
    int b = blockIdx.x, o = threadIdx.x;
    __shared__ float xs[64], rs[128];
    float ex = -INFINITY, fa = INFINITY;
    for (int i = 0; i < 32; i++) {
        float v = x1[(b * 32 + i) * 64 + o];
        ex = fmaxf(ex, v); fa = fminf(fa, v);
    }
    rs[2 * o] = ex; rs[2 * o + 1] = fa;
    xs[o] = x0[b * 64 + o];
    __syncthreads();
    float d0 = 0.0f, d1 = 0.0f;
#pragma unroll 8
    for (int c = 0; c < 64; c++) d0 = fmaf(w_op0[o * 64 + c], xs[c], d0);
#pragma unroll 8
    for (int c = 0; c < 128; c++) d1 = fmaf(w_red0[o * 128 + c], rs[c], d1);
    float s = g_scal[b * 10 + 0] * (d0 + b_op0[o]) + g_scal[b * 10 + 1] * (d1 + b_red0[o]);
    out[b * 64 + o] = g_flags[0] ? sigf(s) : 0.0f;
}

__global__ void o1_kernel(const float* __restrict__ x0, const float* __restrict__ x1,
                          const float* __restrict__ x2,
                          const float* __restrict__ w_exp1, const float* __restrict__ b_exp1,
                          const float* __restrict__ w_op1, const float* __restrict__ b_op1,
                          const float* __restrict__ w_red1, const float* __restrict__ b_red1,
                          float* __restrict__ out) {
    int blk = blockIdx.x;               // b*32+i
    int b = blk >> 5, i = blk & 31, o = threadIdx.x;
    __shared__ float x0s[64], x1s[64], r2s[128];
    float ex = 0.0f, fa = 1.0f;
    const float* base = x2 + (size_t)blk * 2048;
    for (int j = 0; j < 32; j++) {
        if (j == i) continue;
        float v = base[j * 64 + o];
        ex = fmaxf(ex, v); fa = fminf(fa, v);
    }
    r2s[2 * o] = ex; r2s[2 * o + 1] = fa;
    x0s[o] = x0[b * 64 + o];
    x1s[o] = x1[blk * 64 + o];
    __syncthreads();
    float d0 = 0.0f, d1 = 0.0f, d2 = 0.0f;
#pragma unroll 8
    for (int c = 0; c < 64; c++) {
        d0 = fmaf(w_exp1[o * 64 + c], x0s[c], d0);
        d1 = fmaf(w_op1[o * 64 + c], x1s[c], d1);
    }
#pragma unroll 8
    for (int c = 0; c < 128; c++) d2 = fmaf(w_red1[o * 128 + c], r2s[c], d2);
    float s = g_scal[b * 10 + 2] * (d0 + b_exp1[o]) + g_scal[b * 10 + 3] * (d1 + b_op1[o])
            + g_scal[b * 10 + 4] * (d2 + b_red1[o]);
    out[O1_OFF + blk * 64 + o] = g_flags[1] ? sigf(s) : 0.0f;
}

// ---- conflict-free fragment scatter: As[slot=(tile*4+ks)][lane][comp] -------
__device__ __forceinline__ void scatter_Afrag(float* As, int row, int seg, float4 v) {
    int tile = row >> 4, rl = row & 15, g = rl & 7, hi = rl >> 3;
    int ks = seg >> 1, ch2 = seg & 1;
    int comp = hi + 2 * ch2;
    float* p = As + (tile * 4 + ks) * SLOT_PITCH + g * 16 + comp;
    p[0]  = to_tf32(v.x);
    p[4]  = to_tf32(v.y);
    p[8]  = to_tf32(v.z);
    p[12] = to_tf32(v.w);
}

// ------------------------ o3 via mma.sync tf32 -------------------------------
__global__ void __launch_bounds__(256) o3t_kernel(const float* __restrict__ x3,
                                                  float* __restrict__ out) {
    __shared__ float As[32 * SLOT_PITCH];   // 16.9KB
    __shared__ float Ws[2048];              // 8KB, frag order
    int tid = threadIdx.x, wid = tid >> 5, lane = tid & 31;
    int mtp = wid & 3, half = wid >> 2;     // warp: tiles {2mtp,2mtp+1} x nt half
    int bid = blockIdx.x;
    int b = bid >> 8, r = bid & 255, i = r >> 3, j0 = (r & 7) << 2;
    const float* X = x3 + ((size_t)b << 21);
    const float* Wb = g_Wt3 + b * 24576;

    float acc[2][4][4];
#pragma unroll
    for (int t2 = 0; t2 < 2; t2++)
#pragma unroll
        for (int n4 = 0; n4 < 4; n4++)
#pragma unroll
            for (int v = 0; v < 4; v++) acc[t2][n4][v] = 0.0f;

    for (int ch = 0; ch < 12; ch++) {
        int m = ch >> 1, c0 = (ch & 1) << 5;
        __syncthreads();
        const float4* ws = (const float4*)(Wb + ch * 2048);
        ((float4*)Ws)[tid] = ws[tid];
        ((float4*)Ws)[tid + 256] = ws[tid + 256];
#pragma unroll
        for (int it = 0; it < 4; it++) {
            int idx = tid + it * 256;
            int row = idx >> 3, seg = idx & 7;
            int jj = row >> 5, k = row & 31, j = j0 + jj;
            int xr;
            switch (m) {
                case 0:  xr = (i * 32 + j) * 32 + k; break;
                case 1:  xr = (i * 32 + k) * 32 + j; break;
                case 2:  xr = (j * 32 + i) * 32 + k; break;
                case 3:  xr = (k * 32 + i) * 32 + j; break;
                case 4:  xr = (j * 32 + k) * 32 + i; break;
                default: xr = (k * 32 + j) * 32 + i; break;
            }
            float4 v = *(const float4*)(X + (size_t)xr * 64 + c0 + seg * 4);
            scatter_Afrag(As, row, seg, v);
        }
        __syncthreads();
#pragma unroll
        for (int ks = 0; ks < 4; ks++) {
            uint4 a0u = *(const uint4*)(As + ((2 * mtp) * 4 + ks) * SLOT_PITCH + lane * 4);
            uint4 a1u = *(const uint4*)(As + ((2 * mtp + 1) * 4 + ks) * SLOT_PITCH + lane * 4);
            uint32_t a0[4] = {a0u.x, a0u.y, a0u.z, a0u.w};
            uint32_t a1[4] = {a1u.x, a1u.y, a1u.z, a1u.w};
#pragma unroll
            for (int n4 = 0; n4 < 4; n4++) {
                int nt = half * 4 + n4;
                uint2 bu = *(const uint2*)(Ws + ((nt * 4 + ks) * 32 + lane) * 2);
                uint32_t bf[2] = {bu.x, bu.y};
                mma1688(acc[0][n4], a0, bf);
                mma1688(acc[1][n4], a1, bf);
            }
        }
    }

    // epilogue
    int flag = g_flags[3];
    int g = lane >> 2, c2 = (lane & 3) * 2;
#pragma unroll
    for (int t2 = 0; t2 < 2; t2++) {
        int tile = 2 * mtp + t2;
#pragma unroll
        for (int hi = 0; hi < 2; hi++) {
            int row = tile * 16 + g + 8 * hi;
            int jj = row >> 5, kk = row & 31, j = j0 + jj;
            const float* p1p = g_P1 + (((b * 32 + i) * 32 + j) << 6);
            const float* p2p = g_P2 + (((b * 32 + i) * 32 + kk) << 6);
            const float* p3p = g_P3 + (((b * 32 + j) * 32 + kk) << 6);
            float* op = out + O3_OFF + ((((size_t)(b * 32 + i) * 32 + j) * 32 + kk) << 6);
#pragma unroll
            for (int n4 = 0; n4 < 4; n4++) {
                int col = (half * 4 + n4) * 8 + c2;
                float2 p1 = *(const float2*)(p1p + col);
                float2 p2 = *(const float2*)(p2p + col);
                float2 p3 = *(const float2*)(p3p + col);
                float v0 = acc[t2][n4][hi * 2] + p1.x + p2.x + p3.x;
                float v1 = acc[t2][n4][hi * 2 + 1] + p1.y + p2.y + p3.y;
                if (flag) { v0 = sigf(v0); v1 = sigf(v1); }
                else      { v0 = 0.0f; v1 = 0.0f; }
                float2 rr; rr.x = v0; rr.y = v1;
                *(float2*)(op + col) = rr;
            }
        }
    }
}

// ------------------------ o2 via mma.sync tf32: block = (b,i) ----------------
__global__ void __launch_bounds__(128) o2t_kernel(const float* __restrict__ x1,
                                                  const float* __restrict__ x2,
                                                  float* __restrict__ out) {
    __shared__ float As[8 * SLOT_PITCH];    // 2 tiles x 4 ks
    __shared__ float Ws[2048];
    int tid = threadIdx.x, wid = tid >> 5, lane = tid & 31;
    int mt = wid & 1, half = wid >> 1;      // warp: 1 tile x 4 nt
    int bid = blockIdx.x;                   // b*32 + i
    int b = bid >> 5, i = bid & 31;
    const float* Wb = g_Wt2 + (size_t)b * 32768;

    float acc[4][4];
#pragma unroll
    for (int n4 = 0; n4 < 4; n4++)
#pragma unroll
        for (int v = 0; v < 4; v++) acc[n4][v] = 0.0f;

    for (int ch = 0; ch < 16; ch++) {
        __syncthreads();
        const float4* ws = (const float4*)(Wb + ch * 2048);
#pragma unroll
        for (int it = 0; it < 4; it++)
            ((float4*)Ws)[tid + it * 128] = ws[tid + it * 128];
#pragma unroll
        for (int it = 0; it < 2; it++) {
            int idx = tid + it * 128;
            int row = idx >> 3, seg = idx & 7;   // row = j (0..31)
            int j = row;
            int cp = ch * 32 + seg * 4;
            const float* src;
            if (cp < 64)       src = x1 + (b * 32 + i) * 64 + cp;
            else if (cp < 128) src = x1 + (b * 32 + j) * 64 + (cp - 64);
            else if (cp < 192) src = x2 + ((size_t)(b * 32 + i) * 32 + j) * 64 + (cp - 128);
            else if (cp < 256) src = x2 + ((size_t)(b * 32 + j) * 32 + i) * 64 + (cp - 192);
            else if (cp < 384) src = g_r3 + ((size_t)(b * 32 + i) * 32 + j) * 128 + (cp - 256);
            else               src = g_r3 + ((size_t)(b * 32 + j) * 32 + i) * 128 + (cp - 384);
            float4 v = *(const float4*)src;
            scatter_Afrag(As, row, seg, v);
        }
        __syncthreads();
#pragma unroll
        for (int ks = 0; ks < 4; ks++) {
            uint4 au = *(const uint4*)(As + (mt * 4 + ks) * SLOT_PITCH + lane * 4);
            uint32_t a[4] = {au.x, au.y, au.z, au.w};
#pragma unroll
            for (int n4 = 0; n4 < 4; n4++) {
                int nt = half * 4 + n4;
                uint2 bu = *(const uint2*)(Ws + ((nt * 4 + ks) * 32 + lane) * 2);
                uint32_t bf[2] = {bu.x, bu.y};
                mma1688(acc[n4], a, bf);
            }
        }
    }

    int flag = g_flags[2];
    int g = lane >> 2, c2 = (lane & 3) * 2;
#pragma unroll
    for (int hi = 0; hi < 2; hi++) {
        int j = mt * 16 + g + 8 * hi;
        const float* bsp = g_bias2 + b * 64;
        float* op = out + O2_OFF + (((size_t)(b * 32 + i) * 32 + j) << 6);
#pragma unroll
        for (int n4 = 0; n4 < 4; n4++) {
            int col = (half * 4 + n4) * 8 + c2;
            float2 bs = *(const float2*)(bsp + col);
            float v0 = acc[n4][hi * 2] + bs.x;
            float v1 = acc[n4][hi * 2 + 1] + bs.y;
            if (flag) { v0 = sigf(v0); v1 = sigf(v1); }
            else      { v0 = 0.0f; v1 = 0.0f; }
            float2 rr; rr.x = v0; rr.y = v1;
            *(float2*)(op + col) = rr;
        }
    }
}

// ------------------------------- launch -------------------------------------
extern "C" void kernel_launch(void* const* d_in, const int* in_sizes, int n_in,
                              void* d_out, int out_size) {
    const float* x0 = (const float*)d_in[0];
    const float* x1 = (const float*)d_in[1];
    const float* x2 = (const float*)d_in[2];
    const float* x3 = (const float*)d_in[3];
    const float* w_op0 = (const float*)d_in[4];
    const float* b_op0 = (const float*)d_in[5];
    const float* w_red0 = (const float*)d_in[6];
    const float* b_red0 = (const float*)d_in[7];
    const float* w_exp1 = (const float*)d_in[8];
    const float* b_exp1 = (const float*)d_in[9];
    const float* w_op1 = (const float*)d_in[10];
    const float* b_op1 = (const float*)d_in[11];
    const float* w_red1 = (const float*)d_in[12];
    const float* b_red1 = (const float*)d_in[13];
    const float* w_exp2 = (const float*)d_in[14];
    const float* b_exp2 = (const float*)d_in[15];
    const float* w_op2 = (const float*)d_in[16];
    const float* b_op2 = (const float*)d_in[17];
    const float* w_red2 = (const float*)d_in[18];
    const float* b_red2 = (const float*)d_in[19];
    const float* w_exp3 = (const float*)d_in[20];
    const float* b_exp3 = (const float*)d_in[21];
    const float* w_op3 = (const float*)d_in[22];
    const float* b_op3 = (const float*)d_in[23];
    const int* act = (const int*)d_in[24];
    float* out = (float*)d_out;

    prep_kernel<<<64, 256>>>(w_exp3, w_op3, w_exp2, w_op2, w_red2,
                             b_exp3, b_op3, b_exp2, b_op2, b_red2, act);
    y2_kernel<<<256, 384>>>(x2);
    psum_kernel<<<2048, 256>>>();
    o3t_kernel<<<2048, 256>>>(x3, out);
    reduce3_kernel<<<2048, 128>>>(x3);
    o2t_kernel<<<256, 128>>>(x1, x2, out);
    o0_kernel<<<8, 64>>>(x0, x1, w_op0, b_op0, w_red0, b_red0, out);
    o1_kernel<<<256, 64>>>(x0, x1, x2, w_exp1, b_exp1, w_op1, b_op1, w_red1, b_red1, out);
}

// round 8
// speedup vs baseline: 2.1983x; 1.2193x over previous
#include <cuda_runtime.h>
#include <math.h>
#include <stdint.h>

// B=8, n=32, C=64, O=64
// out: concat(o0[8,64], o1[8,32,64], o2[8,32,32,64], o3[8,32,32,32,64]) f32

#define O1_OFF 512
#define O2_OFF 16896
#define O3_OFF 541184

// ---------------- device scratch ----------------
__device__ __align__(16) float g_We3T[384 * 64];
__device__ __align__(16) float g_Wt3[8 * 12 * 2048];   // [b][chunk][frag-order], tf32
__device__ __align__(16) float g_Wt2[8 * 16 * 2048];   // [b][chunk][frag-order], tf32
__device__ __align__(16) float g_bias3[8 * 64];
__device__ __align__(16) float g_bias2[8 * 64];
__device__ __align__(16) float g_scal[8 * 10];
__device__ int g_flags[4];
__device__ __align__(16) float g_r3[8 * 32 * 32 * 128];
__device__ __align__(16) float g_y2[8 * 32 * 32 * 384];
__device__ __align__(16) float g_P1[8 * 32 * 32 * 64];
__device__ __align__(16) float g_P2[8 * 32 * 32 * 64];
__device__ __align__(16) float g_P3[8 * 32 * 32 * 64];

__device__ __forceinline__ float sigf(float x) { return 1.0f / (1.0f + __expf(-x)); }

__device__ __forceinline__ float to_tf32(float x) {
    uint32_t u;
    asm("cvt.rna.tf32.f32 %0, %1;" : "=r"(u) : "f"(x));
    return __uint_as_float(u);
}

// m16n8k8 tf32 mma: D += A * B^T
__device__ __forceinline__ void mma1688(float* d, const uint32_t* a, const uint32_t* b) {
    asm volatile(
        "mma.sync.aligned.m16n8k8.row.col.f32.tf32.tf32.f32 "
        "{%0,%1,%2,%3}, {%4,%5,%6,%7}, {%8,%9}, {%0,%1,%2,%3};"
        : "+f"(d[0]), "+f"(d[1]), "+f"(d[2]), "+f"(d[3])
        : "r"(a[0]), "r"(a[1]), "r"(a[2]), "r"(a[3]), "r"(b[0]), "r"(b[1]));
}

#define APITCH 36   // row-major A staging pitch (floats); bank = 4g+8ks+c -> conflict-free reads

// ------------------------------- prep -------------------------------------
// Wt3/Wt2 in per-chunk B-fragment order:
//   pos = ((nt*4+ks)*32 + lane)*2 + comp; o = nt*8+(lane>>2); k = ks*8+(lane&3)+comp*4
__global__ void prep_kernel(const float* __restrict__ w_exp3, const float* __restrict__ w_op3,
                            const float* __restrict__ w_exp2, const float* __restrict__ w_op2,
                            const float* __restrict__ w_red2, const float* __restrict__ b_exp3,
                            const float* __restrict__ b_op3, const float* __restrict__ b_exp2,
                            const float* __restrict__ b_op2, const float* __restrict__ b_red2,
                            const int* __restrict__ act) {
    int t = blockIdx.x * blockDim.x + threadIdx.x;
    int nth = gridDim.x * blockDim.x;
    if (t < 80) g_scal[t] = (float)act[t];
    if (t == 0) {
        int f0 = 0, f1 = 0, f2 = 0, f3 = 0;
        for (int b = 0; b < 8; b++) {
            f0 |= act[b * 10 + 0] | act[b * 10 + 1];
            f1 |= act[b * 10 + 2] | act[b * 10 + 3] | act[b * 10 + 4];
            f2 |= act[b * 10 + 5] | act[b * 10 + 6] | act[b * 10 + 7];
            f3 |= act[b * 10 + 8] | act[b * 10 + 9];
        }
        g_flags[0] = f0; g_flags[1] = f1; g_flags[2] = f2; g_flags[3] = f3;
    }
    for (int f = t; f < 24576; f += nth) {          // We3T[c*384 + m*64 + o]
        int o = f / 384, r = f % 384, m = r >> 6, c = r & 63;
        g_We3T[c * 384 + m * 64 + o] = w_exp3[f];
    }
    for (int f = t; f < 8 * 24576; f += nth) {
        int b = f / 24576, r = f % 24576;
        int ch = r >> 11, pos = r & 2047;
        int ntks = pos >> 6, lane = (pos >> 1) & 31, comp = pos & 1;
        int o = (ntks >> 2) * 8 + (lane >> 2);
        int k = (ntks & 3) * 8 + (lane & 3) + comp * 4;
        g_Wt3[f] = to_tf32((float)act[b * 10 + 9] * w_op3[o * 384 + ch * 32 + k]);
    }
    for (int f = t; f < 8 * 32768; f += nth) {
        int b = f >> 15, r = f & 32767;
        int ch = r >> 11, pos = r & 2047;
        int ntks = pos >> 6, lane = (pos >> 1) & 31, comp = pos & 1;
        int o = (ntks >> 2) * 8 + (lane >> 2);
        int k = (ntks & 3) * 8 + (lane & 3) + comp * 4;
        int cp = ch * 32 + k;
        float v;
        if (cp < 128)      v = (float)act[b * 10 + 5] * w_exp2[o * 128 + cp];
        else if (cp < 256) v = (float)act[b * 10 + 6] * w_op2[o * 128 + (cp - 128)];
        else               v = (float)act[b * 10 + 7] * w_red2[o * 256 + (cp - 256)];
        g_Wt2[f] = to_tf32(v);
    }
    for (int f = t; f < 512; f += nth) {
        int b = f >> 6, o = f & 63;
        g_bias3[f] = (float)act[b * 10 + 8] * b_exp3[o] + (float)act[b * 10 + 9] * b_op3[o];
        g_bias2[f] = (float)act[b * 10 + 5] * b_exp2[o] + (float)act[b * 10 + 6] * b_op2[o]
                   + (float)act[b * 10 + 7] * b_red2[o];
    }
}

// ----------------------------- reduce3 ----------------------------------
__global__ void __launch_bounds__(128) reduce3_kernel(const float* __restrict__ x3) {
    int sub = threadIdx.x >> 5;
    int c2 = threadIdx.x & 31;
    int blk = blockIdx.x * 4 + sub;             // b*1024 + i*32 + j
    int i = (blk >> 5) & 31, j = blk & 31;
    float ex0 = 0.0f, fa0 = 1.0f, ex1 = 0.0f, fa1 = 1.0f;
    float ex0b = 0.0f, fa0b = 1.0f, ex1b = 0.0f, fa1b = 1.0f;
    if (i != j) {
        const float2* base = (const float2*)(x3 + (size_t)blk * 2048) + c2;
#pragma unroll 4
        for (int k = 0; k < 32; k += 2) {
            float2 v0 = base[k * 32];
            float2 v1 = base[(k + 1) * 32];
            if (k != i && k != j) {
                ex0 = fmaxf(ex0, v0.x); fa0 = fminf(fa0, v0.x);
                ex0b = fmaxf(ex0b, v0.y); fa0b = fminf(fa0b, v0.y);
            }
            if (k + 1 != i && k + 1 != j) {
                ex1 = fmaxf(ex1, v1.x); fa1 = fminf(fa1, v1.x);
                ex1b = fmaxf(ex1b, v1.y); fa1b = fminf(fa1b, v1.y);
            }
        }
    }
    float4 r;
    r.x = fmaxf(ex0, ex1); r.y = fminf(fa0, fa1);
    r.z = fmaxf(ex0b, ex1b); r.w = fminf(fa0b, fa1b);
    if (i == j) { r.x = 0.0f; r.y = 1.0f; r.z = 0.0f; r.w = 1.0f; }
    *(float4*)(g_r3 + (size_t)blk * 128 + 4 * c2) = r;
}

// ------------- y2[b,p,q, m*64+o] = sum_c x2[b,p,q,c] * w_exp3[o, m*64+c] ----
__global__ void __launch_bounds__(384) y2_kernel(const float* __restrict__ x2) {
    __shared__ float Ash[2048];
    __shared__ float Wsh[16 * 384];
    int tid = threadIdx.x;
    int blk = blockIdx.x;
    for (int f = tid; f < 2048; f += 384) Ash[f] = x2[(size_t)blk * 2048 + f];
    float acc[32];
#pragma unroll
    for (int q = 0; q < 32; q++) acc[q] = 0.0f;
    for (int cc = 0; cc < 4; cc++) {
        __syncthreads();
#pragma unroll
        for (int it = 0; it < 16; it++)
            Wsh[it * 384 + tid] = g_We3T[cc * 6144 + it * 384 + tid];
        __syncthreads();
#pragma unroll
        for (int q = 0; q < 32; q++) {
            float s = acc[q];
#pragma unroll
            for (int c2 = 0; c2 < 16; c2++)
                s = fmaf(Ash[q * 64 + cc * 16 + c2], Wsh[c2 * 384 + tid], s);
            acc[q] = s;
        }
    }
#pragma unroll
    for (int q = 0; q < 32; q++)
        g_y2[((size_t)blk * 32 + q) * 384 + tid] = acc[q];
}

// ----------------- pair sums P1/P2/P3 (a8 + bias folded) --------------------
__global__ void psum_kernel() {
    int t = blockIdx.x * blockDim.x + threadIdx.x;
    int o = t & 63, q = (t >> 6) & 31, p = (t >> 11) & 31, b = t >> 16;
    float a8 = g_scal[b * 10 + 8];
    size_t pq = ((size_t)(b * 32 + p) * 32 + q) * 384;
    size_t qp = ((size_t)(b * 32 + q) * 32 + p) * 384;
    g_P1[t] = a8 * (g_y2[pq + o] + g_y2[qp + 128 + o]) + g_bias3[b * 64 + o];
    g_P2[t] = a8 * (g_y2[pq + 64 + o] + g_y2[qp + 192 + o]);
    g_P3[t] = a8 * (g_y2[pq + 256 + o] + g_y2[qp + 320 + o]);
}

// ------------------------------- o0 / o1 (reductions fused) -----------------
__global__ void o0_kernel(const float* __restrict__ x0, const float* __restrict__ x1,
                          const float* __restrict__ w_op0, const float* __restrict__ b_op0,
                          const float* __restrict__ w_red0, const float* __restrict__ b_red0,
                          float* __restrict__ out) {
    int b = blockIdx.x, o = threadIdx.x;
    __shared__ float xs[64], rs[128];
    float ex = -INFINITY, fa = INFINITY;
    for (int i = 0; i < 32; i++) {
        float v = x1[(b * 32 + i) * 64 + o];
        ex = fmaxf(ex, v); fa = fminf(fa, v);
    }
    rs[2 * o] = ex; rs[2 * o + 1] = fa;
    xs[o] = x0[b * 64 + o];
    __syncthreads();
    float d0 = 0.0f, d1 = 0.0f;
#pragma unroll 8
    for (int c = 0; c < 64; c++) d0 = fmaf(w_op0[o * 64 + c], xs[c], d0);
#pragma unroll 8
    for (int c = 0; c < 128; c++) d1 = fmaf(w_red0[o * 128 + c], rs[c], d1);
    float s = g_scal[b * 10 + 0] * (d0 + b_op0[o]) + g_scal[b * 10 + 1] * (d1 + b_red0[o]);
    out[b * 64 + o] = g_flags[0] ? sigf(s) : 0.0f;
}

__global__ void o1_kernel(const float* __restrict__ x0, const float* __restrict__ x1,
                          const float* __restrict__ x2,
                          const float* __restrict__ w_exp1, const float* __restrict__ b_exp1,
                          const float* __restrict__ w_op1, const float* __restrict__ b_op1,
                          const float* __restrict__ w_red1, const float* __restrict__ b_red1,
                          float* __restrict__ out) {
    int blk = blockIdx.x;               // b*32+i
    int b = blk >> 5, i = blk & 31, o = threadIdx.x;
    __shared__ float x0s[64], x1s[64], r2s[128];
    float ex = 0.0f, fa = 1.0f;
    const float* base = x2 + (size_t)blk * 2048;
    for (int j = 0; j < 32; j++) {
        if (j == i) continue;
        float v = base[j * 64 + o];
        ex = fmaxf(ex, v); fa = fminf(fa, v);
    }
    r2s[2 * o] = ex; r2s[2 * o + 1] = fa;
    x0s[o] = x0[b * 64 + o];
    x1s[o] = x1[blk * 64 + o];
    __syncthreads();
    float d0 = 0.0f, d1 = 0.0f, d2 = 0.0f;
#pragma unroll 8
    for (int c = 0; c < 64; c++) {
        d0 = fmaf(w_exp1[o * 64 + c], x0s[c], d0);
        d1 = fmaf(w_op1[o * 64 + c], x1s[c], d1);
    }
#pragma unroll 8
    for (int c = 0; c < 128; c++) d2 = fmaf(w_red1[o * 128 + c], r2s[c], d2);
    float s = g_scal[b * 10 + 2] * (d0 + b_exp1[o]) + g_scal[b * 10 + 3] * (d1 + b_op1[o])
            + g_scal[b * 10 + 4] * (d2 + b_red1[o]);
    out[O1_OFF + blk * 64 + o] = g_flags[1] ? sigf(s) : 0.0f;
}

// ------------------------ o3 via mma.sync tf32, pipelined --------------------
__global__ void __launch_bounds__(256, 3) o3t_kernel(const float* __restrict__ x3,
                                                     float* __restrict__ out) {
    extern __shared__ float sm[];
    float* As = sm;                 // [2][128*APITCH]
    float* Ws = sm + 2 * 128 * APITCH;  // [2][2048]
    int tid = threadIdx.x, wid = tid >> 5, lane = tid & 31;
    int mtp = wid & 3, half = wid >> 2;
    int g = lane >> 2, cc = lane & 3;
    int bid = blockIdx.x;
    int b = bid >> 8, r = bid & 255, i = r >> 3, j0 = (r & 7) << 2;
    const float* X = x3 + ((size_t)b << 21);
    const float* Wb = g_Wt3 + b * 24576;

    int sOf[4], jv[4], kv[4];
#pragma unroll
    for (int it = 0; it < 4; it++) {
        int idx = tid + it * 256;
        int row = idx >> 3, seg = idx & 7;
        sOf[it] = row * APITCH + seg * 4;
        jv[it] = j0 + (row >> 5);
        kv[it] = row & 31;
        (void)seg;
    }
    int segOf[4];
#pragma unroll
    for (int it = 0; it < 4; it++) segOf[it] = ((tid + it * 256) & 7) * 4;

    float4 av[4], wv[2];
    float acc[2][4][4];
#pragma unroll
    for (int t2 = 0; t2 < 2; t2++)
#pragma unroll
        for (int n4 = 0; n4 < 4; n4++)
#pragma unroll
            for (int v = 0; v < 4; v++) acc[t2][n4][v] = 0.0f;

#define LOAD_CH(ch) do {                                                        \
    int m_ = (ch) >> 1, c0_ = ((ch) & 1) << 5;                                  \
    int sj_, sk_, base_;                                                        \
    switch (m_) {                                                               \
        case 0: base_ = i * 1024; sj_ = 32;   sk_ = 1;    break;                \
        case 1: base_ = i * 1024; sj_ = 1;    sk_ = 32;   break;                \
        case 2: base_ = i * 32;   sj_ = 1024; sk_ = 1;    break;                \
        case 3: base_ = i * 32;   sj_ = 1;    sk_ = 1024; break;                \
        case 4: base_ = i;        sj_ = 1024; sk_ = 32;   break;                \
        default: base_ = i;       sj_ = 32;   sk_ = 1024; break;                \
    }                                                                           \
    _Pragma("unroll")                                                           \
    for (int it = 0; it < 4; it++)                                              \
        av[it] = *(const float4*)(X + (size_t)(base_ + jv[it] * sj_ + kv[it] * sk_) * 64 \
                                  + c0_ + segOf[it]);                           \
    const float4* ws_ = (const float4*)(Wb + (ch) * 2048);                      \
    wv[0] = ws_[tid]; wv[1] = ws_[tid + 256];                                   \
} while (0)

#define STORE_CH(p) do {                                                        \
    float* Ap_ = As + (p) * (128 * APITCH);                                     \
    _Pragma("unroll")                                                           \
    for (int it = 0; it < 4; it++) {                                            \
        float4 v_ = av[it];                                                     \
        v_.x = to_tf32(v_.x); v_.y = to_tf32(v_.y);                             \
        v_.z = to_tf32(v_.z); v_.w = to_tf32(v_.w);                             \
        *(float4*)(Ap_ + sOf[it]) = v_;                                         \
    }                                                                           \
    float* Wp_ = Ws + (p) * 2048;                                               \
    ((float4*)Wp_)[tid] = wv[0]; ((float4*)Wp_)[tid + 256] = wv[1];             \
} while (0)

    LOAD_CH(0);
    STORE_CH(0);
    __syncthreads();

    for (int ch = 0; ch < 12; ch++) {
        int p = ch & 1;
        if (ch < 11) LOAD_CH(ch + 1);
        const float* Ap = As + p * (128 * APITCH);
        const float* Wp = Ws + p * 2048;
#pragma unroll
        for (int ks = 0; ks < 4; ks++) {
            const float* pa = Ap + (mtp * 32 + g) * APITCH + ks * 8 + cc;
            uint32_t a0[4], a1[4];
            a0[0] = __float_as_uint(pa[0]);
            a0[1] = __float_as_uint(pa[8 * APITCH]);
            a0[2] = __float_as_uint(pa[4]);
            a0[3] = __float_as_uint(pa[8 * APITCH + 4]);
            const float* pb = pa + 16 * APITCH;
            a1[0] = __float_as_uint(pb[0]);
            a1[1] = __float_as_uint(pb[8 * APITCH]);
            a1[2] = __float_as_uint(pb[4]);
            a1[3] = __float_as_uint(pb[8 * APITCH + 4]);
#pragma unroll
            for (int n4 = 0; n4 < 4; n4++) {
                int nt = half * 4 + n4;
                uint2 bu = *(const uint2*)(Wp + ((nt * 4 + ks) * 32 + lane) * 2);
                uint32_t bf[2] = {bu.x, bu.y};
                mma1688(acc[0][n4], a0, bf);
                mma1688(acc[1][n4], a1, bf);
            }
        }
        if (ch < 11) STORE_CH(1 - p);
        __syncthreads();
    }
#undef LOAD_CH
#undef STORE_CH

    // epilogue
    int flag = g_flags[3];
    int c2 = (lane & 3) * 2;
#pragma unroll
    for (int t2 = 0; t2 < 2; t2++) {
        int tile = 2 * mtp + t2;
#pragma unroll
        for (int hi = 0; hi < 2; hi++) {
            int row = tile * 16 + g + 8 * hi;
            int jj = row >> 5, kk = row & 31, j = j0 + jj;
            const float* p1p = g_P1 + (((b * 32 + i) * 32 + j) << 6);
            const float* p2p = g_P2 + (((b * 32 + i) * 32 + kk) << 6);
            const float* p3p = g_P3 + (((b * 32 + j) * 32 + kk) << 6);
            float* op = out + O3_OFF + ((((size_t)(b * 32 + i) * 32 + j) * 32 + kk) << 6);
#pragma unroll
            for (int n4 = 0; n4 < 4; n4++) {
                int col = (half * 4 + n4) * 8 + c2;
                float2 p1 = *(const float2*)(p1p + col);
                float2 p2 = *(const float2*)(p2p + col);
                float2 p3 = *(const float2*)(p3p + col);
                float v0 = acc[t2][n4][hi * 2] + p1.x + p2.x + p3.x;
                float v1 = acc[t2][n4][hi * 2 + 1] + p1.y + p2.y + p3.y;
                if (flag) { v0 = sigf(v0); v1 = sigf(v1); }
                else      { v0 = 0.0f; v1 = 0.0f; }
                float2 rr; rr.x = v0; rr.y = v1;
                *(float2*)(op + col) = rr;
            }
        }
    }
}

// ------------------------ o2 via mma.sync tf32, pipelined --------------------
__global__ void __launch_bounds__(128) o2t_kernel(const float* __restrict__ x1,
                                                  const float* __restrict__ x2,
                                                  float* __restrict__ out) {
    __shared__ float As[2][32 * APITCH];
    __shared__ float Ws[2][2048];
    int tid = threadIdx.x, wid = tid >> 5, lane = tid & 31;
    int mt = wid & 1, half = wid >> 1;
    int g = lane >> 2, cc = lane & 3;
    int bid = blockIdx.x;                   // b*32 + i
    int b = bid >> 5, i = bid & 31;
    const float* Wb = g_Wt2 + (size_t)b * 32768;

    int sOf[2], jv[2], segOf[2];
#pragma unroll
    for (int it = 0; it < 2; it++) {
        int idx = tid + it * 128;
        int row = idx >> 3, seg = idx & 7;
        sOf[it] = row * APITCH + seg * 4;
        jv[it] = row;
        segOf[it] = seg * 4;
    }

    float4 av[2], wv[4];
    float acc[4][4];
#pragma unroll
    for (int n4 = 0; n4 < 4; n4++)
#pragma unroll
        for (int v = 0; v < 4; v++) acc[n4][v] = 0.0f;

#define LOAD_CH2(ch) do {                                                        \
    _Pragma("unroll")                                                            \
    for (int it = 0; it < 2; it++) {                                             \
        int j_ = jv[it];                                                         \
        int cp_ = (ch) * 32 + segOf[it];                                         \
        const float* src_;                                                       \
        if (cp_ < 64)       src_ = x1 + (b * 32 + i) * 64 + cp_;                 \
        else if (cp_ < 128) src_ = x1 + (b * 32 + j_) * 64 + (cp_ - 64);         \
        else if (cp_ < 192) src_ = x2 + ((size_t)(b * 32 + i) * 32 + j_) * 64 + (cp_ - 128); \
        else if (cp_ < 256) src_ = x2 + ((size_t)(b * 32 + j_) * 32 + i) * 64 + (cp_ - 192); \
        else if (cp_ < 384) src_ = g_r3 + ((size_t)(b * 32 + i) * 32 + j_) * 128 + (cp_ - 256); \
        else                src_ = g_r3 + ((size_t)(b * 32 + j_) * 32 + i) * 128 + (cp_ - 384); \
        av[it] = *(const float4*)src_;                                           \
    }                                                                            \
    const float4* ws_ = (const float4*)(Wb + (ch) * 2048);                       \
    _Pragma("unroll")                                                            \
    for (int it = 0; it < 4; it++) wv[it] = ws_[tid + it * 128];                 \
} while (0)

#define STORE_CH2(p) do {                                                        \
    _Pragma("unroll")                                                            \
    for (int it = 0; it < 2; it++) {                                             \
        float4 v_ = av[it];                                                      \
        v_.x = to_tf32(v_.x); v_.y = to_tf32(v_.y);                              \
        v_.z = to_tf32(v_.z); v_.w = to_tf32(v_.w);                              \
        *(float4*)(&As[p][0] + sOf[it]) = v_;                                    \
    }                                                                            \
    _Pragma("unroll")                                                            \
    for (int it = 0; it < 4; it++) ((float4*)&Ws[p][0])[tid + it * 128] = wv[it];\
} while (0)

    LOAD_CH2(0);
    STORE_CH2(0);
    __syncthreads();

    for (int ch = 0; ch < 16; ch++) {
        int p = ch & 1;
        if (ch < 15) LOAD_CH2(ch + 1);
        const float* Ap = &As[p][0];
        const float* Wp = &Ws[p][0];
#pragma unroll
        for (int ks = 0; ks < 4; ks++) {
            const float* pa = Ap + (mt * 16 + g) * APITCH + ks * 8 + cc;
            uint32_t a[4];
            a[0] = __float_as_uint(pa[0]);
            a[1] = __float_as_uint(pa[8 * APITCH]);
            a[2] = __float_as_uint(pa[4]);
            a[3] = __float_as_uint(pa[8 * APITCH + 4]);
#pragma unroll
            for (int n4 = 0; n4 < 4; n4++) {
                int nt = half * 4 + n4;
                uint2 bu = *(const uint2*)(Wp + ((nt * 4 + ks) * 32 + lane) * 2);
                uint32_t bf[2] = {bu.x, bu.y};
                mma1688(acc[n4], a, bf);
            }
        }
        if (ch < 15) STORE_CH2(1 - p);
        __syncthreads();
    }
#undef LOAD_CH2
#undef STORE_CH2

    int flag = g_flags[2];
    int c2 = (lane & 3) * 2;
#pragma unroll
    for (int hi = 0; hi < 2; hi++) {
        int j = mt * 16 + g + 8 * hi;
        const float* bsp = g_bias2 + b * 64;
        float* op = out + O2_OFF + (((size_t)(b * 32 + i) * 32 + j) << 6);
#pragma unroll
        for (int n4 = 0; n4 < 4; n4++) {
            int col = (half * 4 + n4) * 8 + c2;
            float2 bs = *(const float2*)(bsp + col);
            float v0 = acc[n4][hi * 2] + bs.x;
            float v1 = acc[n4][hi * 2 + 1] + bs.y;
            if (flag) { v0 = sigf(v0); v1 = sigf(v1); }
            else      { v0 = 0.0f; v1 = 0.0f; }
            float2 rr; rr.x = v0; rr.y = v1;
            *(float2*)(op + col) = rr;
        }
    }
}

// ------------------------------- launch -------------------------------------
extern "C" void kernel_launch(void* const* d_in, const int* in_sizes, int n_in,
                              void* d_out, int out_size) {
    const float* x0 = (const float*)d_in[0];
    const float* x1 = (const float*)d_in[1];
    const float* x2 = (const float*)d_in[2];
    const float* x3 = (const float*)d_in[3];
    const float* w_op0 = (const float*)d_in[4];
    const float* b_op0 = (const float*)d_in[5];
    const float* w_red0 = (const float*)d_in[6];
    const float* b_red0 = (const float*)d_in[7];
    const float* w_exp1 = (const float*)d_in[8];
    const float* b_exp1 = (const float*)d_in[9];
    const float* w_op1 = (const float*)d_in[10];
    const float* b_op1 = (const float*)d_in[11];
    const float* w_red1 = (const float*)d_in[12];
    const float* b_red1 = (const float*)d_in[13];
    const float* w_exp2 = (const float*)d_in[14];
    const float* b_exp2 = (const float*)d_in[15];
    const float* w_op2 = (const float*)d_in[16];
    const float* b_op2 = (const float*)d_in[17];
    const float* w_red2 = (const float*)d_in[18];
    const float* b_red2 = (const float*)d_in[19];
    const float* w_exp3 = (const float*)d_in[20];
    const float* b_exp3 = (const float*)d_in[21];
    const float* w_op3 = (const float*)d_in[22];
    const float* b_op3 = (const float*)d_in[23];
    const int* act = (const int*)d_in[24];
    float* out = (float*)d_out;

    const int O3T_SMEM = (2 * 128 * APITCH + 2 * 2048) * 4;   // 53248 B
    cudaFuncSetAttribute(o3t_kernel, cudaFuncAttributeMaxDynamicSharedMemorySize, O3T_SMEM);

    prep_kernel<<<64, 256>>>(w_exp3, w_op3, w_exp2, w_op2, w_red2,
                             b_exp3, b_op3, b_exp2, b_op2, b_red2, act);
    y2_kernel<<<256, 384>>>(x2);
    psum_kernel<<<2048, 256>>>();
    o3t_kernel<<<2048, 256, O3T_SMEM>>>(x3, out);
    reduce3_kernel<<<2048, 128>>>(x3);
    o2t_kernel<<<256, 128>>>(x1, x2, out);
    o0_kernel<<<8, 64>>>(x0, x1, w_op0, b_op0, w_red0, b_red0, out);
    o1_kernel<<<256, 64>>>(x0, x1, x2, w_exp1, b_exp1, w_op1, b_op1, w_red1, b_red1, out);
}